// round 9
// baseline (speedup 1.0000x reference)
#include <cuda_runtime.h>
#include <cuda_bf16.h>
#include <cuda_fp16.h>
#include <cstdint>

#define NTOK 8192
#define DIN  1024
#define DH   128
#define NSPLIT 2
#define KEYS_PER_SPLIT (NTOK / NSPLIT)

// Pre-split inputs (prep kernel).
__device__ __nv_bfloat16 g_Xhi[NTOK * DIN], g_Xlo[NTOK * DIN];
__device__ __nv_bfloat16 g_Whi[3 * DIN * DH], g_Wlo[3 * DIN * DH];
// Split operands produced by the projection kernel.
__device__ __nv_bfloat16 g_Qhi[NTOK * DH], g_Qlo[NTOK * DH]; // pre-scaled by (1/sqrt d)*log2 e
__device__ __nv_bfloat16 g_Khi[NTOK * DH], g_Klo[NTOK * DH];
__device__ __half        g_Vhi[NTOK * DH];
// Split-KV partials.
__device__ float g_Opart[NSPLIT * NTOK * DH];
__device__ float g_Mpart[NSPLIT * NTOK];
__device__ float g_Lpart[NSPLIT * NTOK];

__device__ __forceinline__ uint32_t smem_u32(const void* p) {
  uint32_t a;
  asm("{ .reg .u64 t; cvta.to.shared.u64 t, %1; cvt.u32.u64 %0, t; }"
      : "=r"(a) : "l"(p));
  return a;
}
__device__ __forceinline__ float ex2f(float x) {
  float y; asm("ex2.approx.ftz.f32 %0, %1;" : "=f"(y) : "f"(x)); return y;
}
__device__ __forceinline__ void ldsm4(uint32_t* r, uint32_t addr) {
  asm volatile("ldmatrix.sync.aligned.m8n8.x4.shared.b16 {%0,%1,%2,%3}, [%4];"
               : "=r"(r[0]), "=r"(r[1]), "=r"(r[2]), "=r"(r[3]) : "r"(addr));
}
__device__ __forceinline__ void ldsm4t(uint32_t* r, uint32_t addr) {
  asm volatile("ldmatrix.sync.aligned.m8n8.x4.trans.shared.b16 {%0,%1,%2,%3}, [%4];"
               : "=r"(r[0]), "=r"(r[1]), "=r"(r[2]), "=r"(r[3]) : "r"(addr));
}
__device__ __forceinline__ void mma_bf16(float* d, const uint32_t* a,
                                         const uint32_t* b) {
  asm volatile(
      "mma.sync.aligned.m16n8k16.row.col.f32.bf16.bf16.f32 "
      "{%0,%1,%2,%3}, {%4,%5,%6,%7}, {%8,%9}, {%0,%1,%2,%3};"
      : "+f"(d[0]), "+f"(d[1]), "+f"(d[2]), "+f"(d[3])
      : "r"(a[0]), "r"(a[1]), "r"(a[2]), "r"(a[3]), "r"(b[0]), "r"(b[1]));
}
__device__ __forceinline__ void mma_f16(float* d, const uint32_t* a,
                                        const uint32_t* b) {
  asm volatile(
      "mma.sync.aligned.m16n8k16.row.col.f32.f16.f16.f32 "
      "{%0,%1,%2,%3}, {%4,%5,%6,%7}, {%8,%9}, {%0,%1,%2,%3};"
      : "+f"(d[0]), "+f"(d[1]), "+f"(d[2]), "+f"(d[3])
      : "r"(a[0]), "r"(a[1]), "r"(a[2]), "r"(a[3]), "r"(b[0]), "r"(b[1]));
}
__device__ __forceinline__ void cpa16(uint32_t dst, const void* src) {
  asm volatile("cp.async.cg.shared.global [%0], [%1], 16;" :: "r"(dst), "l"(src));
}
#define CP_COMMIT() asm volatile("cp.async.commit_group;" ::: "memory")
#define CP_WAIT1() asm volatile("cp.async.wait_group 1;" ::: "memory")
#define CP_WAIT0() asm volatile("cp.async.wait_group 0;" ::: "memory")

// ---------------------------------------------------------------------------
// Prep kernel: split x and W (fp32 -> bf16 hi/lo) in one launch.
// blocks [0, 8192): x; blocks [8192, 8576): W (y = (b-8192)>>7).
// ---------------------------------------------------------------------------
__global__ __launch_bounds__(256) void split_all_kernel(
    const float* __restrict__ x, const float* __restrict__ Wq,
    const float* __restrict__ Wk, const float* __restrict__ Wv) {
  int b = blockIdx.x;
  const float* src;
  __nv_bfloat16 *dhi, *dlo;
  size_t i;
  float sc = 1.0f;
  if (b < NTOK * DIN / 1024) {
    src = x;  dhi = g_Xhi;  dlo = g_Xlo;
    i = ((size_t)b * 256 + threadIdx.x) * 4;
  } else {
    int w = b - NTOK * DIN / 1024;
    int y = w >> 7, bx = w & 127;
    if (y == 0) { src = Wq; sc = 0.08838834764831845f * 1.4426950408889634f; }
    else if (y == 1) src = Wk;
    else src = Wv;
    i = ((size_t)bx * 256 + threadIdx.x) * 4;
    dhi = g_Whi + (size_t)y * DIN * DH;
    dlo = g_Wlo + (size_t)y * DIN * DH;
  }
  float4 v = *(const float4*)(src + i);
  v.x *= sc; v.y *= sc; v.z *= sc; v.w *= sc;
  __nv_bfloat16 h0 = __float2bfloat16_rn(v.x), h1 = __float2bfloat16_rn(v.y);
  __nv_bfloat16 h2 = __float2bfloat16_rn(v.z), h3 = __float2bfloat16_rn(v.w);
  __nv_bfloat162 hh0 = __halves2bfloat162(h0, h1), hh1 = __halves2bfloat162(h2, h3);
  __nv_bfloat162 ll0 = __halves2bfloat162(
      __float2bfloat16_rn(v.x - __bfloat162float(h0)),
      __float2bfloat16_rn(v.y - __bfloat162float(h1)));
  __nv_bfloat162 ll1 = __halves2bfloat162(
      __float2bfloat16_rn(v.z - __bfloat162float(h2)),
      __float2bfloat16_rn(v.w - __bfloat162float(h3)));
  *(uint2*)&dhi[i] = make_uint2(*(uint32_t*)&hh0, *(uint32_t*)&hh1);
  *(uint2*)&dlo[i] = make_uint2(*(uint32_t*)&ll0, *(uint32_t*)&ll1);
}

// ---------------------------------------------------------------------------
// Kernel 1: QKV projection GEMM, BM=64, 128 threads, 2 CTAs/SM.
// ---------------------------------------------------------------------------
#define XROW 144
#define WROW 272
#define PSTAGE 53248
#define SMEM_PROJ (2 * PSTAGE)

__device__ __forceinline__ void proj_issue(int tid, int mb, int y, int k0,
                                           uint32_t dstbase) {
#pragma unroll
  for (int it = 0; it < 8; it++) {
    int idx = tid + it * 128;
    int arr = idx >> 9, w = idx & 511;
    int r = w >> 3, c = w & 7;
    const __nv_bfloat16* src = (arr ? g_Xlo : g_Xhi) +
                               (size_t)(mb + r) * DIN + k0 + c * 8;
    cpa16(dstbase + arr * 9216 + r * XROW + c * 16, src);
  }
#pragma unroll
  for (int it = 0; it < 16; it++) {
    int idx = tid + it * 128;
    int arr = idx >> 10, w = idx & 1023;
    int r = w >> 4, c = w & 15;
    const __nv_bfloat16* src = (arr ? g_Wlo : g_Whi) +
                               (size_t)y * DIN * DH + (size_t)(k0 + r) * DH + c * 8;
    cpa16(dstbase + 18432 + arr * 17408 + r * WROW + c * 16, src);
  }
}

__global__ __launch_bounds__(128, 2) void qkv_proj_mma() {
  extern __shared__ char smc[];
  const int tid = threadIdx.x;
  const int lane = tid & 31, warp = tid >> 5;
  const int wm = warp * 16;
  const int mb = blockIdx.x * 64;
  const int y = blockIdx.y;
  const uint32_t sb = smem_u32(smc);

  float acc[16][4];
#pragma unroll
  for (int f = 0; f < 16; f++)
#pragma unroll
    for (int e = 0; e < 4; e++) acc[f][e] = 0.f;

  const uint32_t ah_addr = sb + (uint32_t)(wm + (lane & 15)) * XROW +
                           (lane >> 4) * 16;
  const uint32_t bh_addr = sb + 18432 +
                           (uint32_t)((lane & 7) + ((lane >> 3) & 1) * 8) * WROW +
                           ((lane >> 4) & 1) * 16;

  proj_issue(tid, mb, y, 0, sb);           CP_COMMIT();
  proj_issue(tid, mb, y, 64, sb + PSTAGE); CP_COMMIT();

  const int NT = DIN / 64;   // 16
  for (int t = 0; t < NT; t++) {
    if (t + 1 < NT) CP_WAIT1(); else CP_WAIT0();
    __syncthreads();
    uint32_t bo = (uint32_t)(t & 1) * PSTAGE;
#pragma unroll
    for (int j = 0; j < 4; j++) {
      uint32_t ah[4], al[4];
      ldsm4(ah, ah_addr + bo + j * 32);
      ldsm4(al, ah_addr + bo + 9216 + j * 32);
#pragma unroll
      for (int f2 = 0; f2 < 8; f2++) {
        uint32_t bh[4], bl[4];
        uint32_t a = bh_addr + bo + (uint32_t)(j * 16) * WROW + f2 * 32;
        ldsm4t(bh, a);
        ldsm4t(bl, a + 17408);
        mma_bf16(acc[2 * f2], ah, bh);
        mma_bf16(acc[2 * f2 + 1], ah, bh + 2);
        mma_bf16(acc[2 * f2], ah, bl);
        mma_bf16(acc[2 * f2 + 1], ah, bl + 2);
        mma_bf16(acc[2 * f2], al, bh);
        mma_bf16(acc[2 * f2 + 1], al, bh + 2);
      }
    }
    __syncthreads();
    if (t + 2 < NT) { proj_issue(tid, mb, y, (t + 2) * 64, sb + bo); }
    CP_COMMIT();
  }

  int r0 = mb + wm + (lane >> 2), r1 = r0 + 8;
  int cb = 2 * (lane & 3);
#pragma unroll
  for (int f = 0; f < 16; f++) {
    int c = 8 * f + cb;
    float v0 = acc[f][0], v1 = acc[f][1], v2 = acc[f][2], v3 = acc[f][3];
    if (y == 2) {
      *(__half2*)&g_Vhi[(size_t)r0 * DH + c] = __floats2half2_rn(v0, v1);
      *(__half2*)&g_Vhi[(size_t)r1 * DH + c] = __floats2half2_rn(v2, v3);
    } else {
      __nv_bfloat16 h0 = __float2bfloat16_rn(v0), h1 = __float2bfloat16_rn(v1);
      __nv_bfloat16 h2 = __float2bfloat16_rn(v2), h3 = __float2bfloat16_rn(v3);
      __nv_bfloat16* hi = y ? g_Khi : g_Qhi;
      __nv_bfloat16* lo = y ? g_Klo : g_Qlo;
      *(__nv_bfloat162*)&hi[(size_t)r0 * DH + c] = __halves2bfloat162(h0, h1);
      *(__nv_bfloat162*)&hi[(size_t)r1 * DH + c] = __halves2bfloat162(h2, h3);
      *(__nv_bfloat162*)&lo[(size_t)r0 * DH + c] = __halves2bfloat162(
          __float2bfloat16_rn(v0 - __bfloat162float(h0)),
          __float2bfloat16_rn(v1 - __bfloat162float(h1)));
      *(__nv_bfloat162*)&lo[(size_t)r1 * DH + c] = __halves2bfloat162(
          __float2bfloat16_rn(v2 - __bfloat162float(h2)),
          __float2bfloat16_rn(v3 - __bfloat162float(h3)));
    }
  }
}

// ---------------------------------------------------------------------------
// Kernel 2: flash attention, BM=128 (8 warps, 256 thr), BN=64, split-KV x2.
// Q fragments resident in REGISTERS (no per-tile Q smem reads); single sf
// buffer; 3-stage cp.async ring with 2-deep prefetch, one barrier per tile.
// PV = Phi * Vhi (fp16).  Stage: KHI 0, KLO 17408, VHI 34816; 3 x 52224.
// ---------------------------------------------------------------------------
#define ROWB 272
#define SKLO 17408
#define SVHI 34816
#define FSTAGE 52224
#define SMEM_FLASH (3 * FSTAGE)
#define FNT (KEYS_PER_SPLIT / 64)   // 64 tiles

__device__ __forceinline__ void flash_issue(int tid, int n0, uint32_t dstbase) {
#pragma unroll
  for (int it = 0; it < 12; it++) {
    int idx = tid + it * 256;
    int arr = idx >> 10, w = idx & 1023;
    int r = w >> 4, c = w & 15;
    const __nv_bfloat16* srcb;
    if (arr == 0)      srcb = g_Khi;
    else if (arr == 1) srcb = g_Klo;
    else               srcb = (const __nv_bfloat16*)g_Vhi;
    cpa16(dstbase + arr * 17408 + r * ROWB + c * 16,
          srcb + (size_t)(n0 + r) * DH + c * 8);
  }
}

__global__ __launch_bounds__(256, 1) void flash_mma(int dummy) {
  extern __shared__ char smc[];
  const int tid = threadIdx.x;
  const int lane = tid & 31, warp = tid >> 5;
  const int wm = warp * 16;
  const int mb = blockIdx.x * 128;
  const int split = blockIdx.y;
  const int nbase = split * KEYS_PER_SPLIT;
  const uint32_t sb = smem_u32(smc);

  // --- Stage Q transiently into stages 0..1 area, load fragments, then
  //     start the K/V ring. Qhi at [0, 34816), Qlo at [34816, 69632). ---
#pragma unroll
  for (int it = 0; it < 8; it++) {
    int idx = tid + it * 256;
    int r = idx >> 4, c = idx & 15;
    size_t g = (size_t)(mb + r) * DH + c * 8;
    *(float4*)(smc + r * ROWB + c * 16) = *(const float4*)(g_Qhi + g);
    *(float4*)(smc + 34816 + r * ROWB + c * 16) = *(const float4*)(g_Qlo + g);
  }
  __syncthreads();

  uint32_t qh[8][4], ql[8][4];
  {
    uint32_t aoff = sb + (uint32_t)(wm + (lane & 15)) * ROWB + (lane >> 4) * 16;
#pragma unroll
    for (int j = 0; j < 8; j++) {
      ldsm4(qh[j], aoff + j * 32);
      ldsm4(ql[j], aoff + 34816 + j * 32);
    }
  }
  __syncthreads();   // Q area dead -> stages 0/1 reusable.

  flash_issue(tid, nbase, sb);                  CP_COMMIT();   // g0 -> stage 0
  flash_issue(tid, nbase + 64, sb + FSTAGE);    CP_COMMIT();   // g1 -> stage 1

  const uint32_t kaddr = sb + (uint32_t)((lane & 7) + ((lane >> 4) << 3)) * ROWB +
                         ((lane >> 3) & 1) * 16;
  const uint32_t vaddr = sb + (uint32_t)((lane & 7) + (((lane >> 3) & 1) << 3)) * ROWB +
                         ((lane >> 4) & 1) * 16 + SVHI;

  float of[16][4];
#pragma unroll
  for (int f = 0; f < 16; f++)
#pragma unroll
    for (int e = 0; e < 4; e++) of[f][e] = 0.f;
  float mrow0 = -1e30f, mrow1 = -1e30f, l0 = 0.f, l1 = 0.f;

  for (int t = 0; t < FNT; t++) {
    // Wait for group t: with issue depth 2, WAIT1 retires g(t) except on the
    // final tile where only g(t) is outstanding -> WAIT0.
    if (t < FNT - 1) CP_WAIT1(); else CP_WAIT0();
    __syncthreads();   // stage t%3 visible to all; stage (t+2)%3 free.
    if (t + 2 < FNT) {
      flash_issue(tid, nbase + (t + 2) * 64,
                  sb + (uint32_t)((t + 2) % 3) * FSTAGE);
      CP_COMMIT();
    }
    const uint32_t bo = (uint32_t)(t % 3) * FSTAGE;

    // ---- S = Q K^T (16x64 per warp, Q from registers) ----
    float sf[8][4];
#pragma unroll
    for (int f = 0; f < 8; f++)
#pragma unroll
      for (int e = 0; e < 4; e++) sf[f][e] = 0.f;
#pragma unroll
    for (int j = 0; j < 8; j++) {
#pragma unroll
      for (int f2 = 0; f2 < 4; f2++) {
        uint32_t bh[4], bl[4];
        uint32_t a = kaddr + bo + (uint32_t)(f2 * 16) * ROWB + j * 32;
        ldsm4(bh, a);
        ldsm4(bl, a + SKLO);
        mma_bf16(sf[2 * f2], qh[j], bh);
        mma_bf16(sf[2 * f2 + 1], qh[j], bh + 2);
        mma_bf16(sf[2 * f2], qh[j], bl);
        mma_bf16(sf[2 * f2 + 1], qh[j], bl + 2);
        mma_bf16(sf[2 * f2], ql[j], bh);
        mma_bf16(sf[2 * f2 + 1], ql[j], bh + 2);
      }
    }

    // ---- online softmax (base-2 logits) ----
    float mx0 = sf[0][0], mx1 = sf[0][2];
#pragma unroll
    for (int f = 0; f < 8; f++) {
      mx0 = fmaxf(mx0, fmaxf(sf[f][0], sf[f][1]));
      mx1 = fmaxf(mx1, fmaxf(sf[f][2], sf[f][3]));
    }
    mx0 = fmaxf(mx0, __shfl_xor_sync(0xffffffffu, mx0, 1));
    mx0 = fmaxf(mx0, __shfl_xor_sync(0xffffffffu, mx0, 2));
    mx1 = fmaxf(mx1, __shfl_xor_sync(0xffffffffu, mx1, 1));
    mx1 = fmaxf(mx1, __shfl_xor_sync(0xffffffffu, mx1, 2));

    float mn0 = fmaxf(mrow0, mx0), mn1 = fmaxf(mrow1, mx1);
    float a0 = ex2f(mrow0 - mn0), a1 = ex2f(mrow1 - mn1);
    mrow0 = mn0; mrow1 = mn1;

    float s0 = 0.f, s1 = 0.f;
#pragma unroll
    for (int f = 0; f < 8; f++) {
      sf[f][0] = ex2f(sf[f][0] - mn0);
      sf[f][1] = ex2f(sf[f][1] - mn0);
      sf[f][2] = ex2f(sf[f][2] - mn1);
      sf[f][3] = ex2f(sf[f][3] - mn1);
      s0 += sf[f][0] + sf[f][1];
      s1 += sf[f][2] + sf[f][3];
    }
    s0 += __shfl_xor_sync(0xffffffffu, s0, 1);
    s0 += __shfl_xor_sync(0xffffffffu, s0, 2);
    s1 += __shfl_xor_sync(0xffffffffu, s1, 1);
    s1 += __shfl_xor_sync(0xffffffffu, s1, 2);
    l0 = l0 * a0 + s0;
    l1 = l1 * a1 + s1;

    if (!__all_sync(0xffffffffu, (__float_as_uint(a0) == 0x3f800000u) &&
                                (__float_as_uint(a1) == 0x3f800000u))) {
#pragma unroll
      for (int f = 0; f < 16; f++) {
        of[f][0] *= a0;  of[f][1] *= a0;
        of[f][2] *= a1;  of[f][3] *= a1;
      }
    }

    // ---- O += P V ----
#pragma unroll
    for (int j2 = 0; j2 < 4; j2++) {
      uint32_t ph[4];
      __half2 h;
      h = __floats2half2_rn(sf[2 * j2][0], sf[2 * j2][1]);         ph[0] = *(uint32_t*)&h;
      h = __floats2half2_rn(sf[2 * j2][2], sf[2 * j2][3]);         ph[1] = *(uint32_t*)&h;
      h = __floats2half2_rn(sf[2 * j2 + 1][0], sf[2 * j2 + 1][1]); ph[2] = *(uint32_t*)&h;
      h = __floats2half2_rn(sf[2 * j2 + 1][2], sf[2 * j2 + 1][3]); ph[3] = *(uint32_t*)&h;
      uint32_t ka = vaddr + bo + (uint32_t)(j2 * 16) * ROWB;
#pragma unroll
      for (int f2 = 0; f2 < 8; f2++) {
        uint32_t bv[4];
        ldsm4t(bv, ka + f2 * 32);
        mma_f16(of[2 * f2], ph, bv);
        mma_f16(of[2 * f2 + 1], ph, bv + 2);
      }
    }
  }

  // ---- write partials ----
  int r0 = lane >> 2, r1 = r0 + 8;
  int cbase = 2 * (lane & 3);
  size_t orow0 = (size_t)(split * NTOK + mb + wm + r0) * DH;
  size_t orow1 = (size_t)(split * NTOK + mb + wm + r1) * DH;
#pragma unroll
  for (int f = 0; f < 16; f++) {
    *(float2*)&g_Opart[orow0 + 8 * f + cbase] = make_float2(of[f][0], of[f][1]);
    *(float2*)&g_Opart[orow1 + 8 * f + cbase] = make_float2(of[f][2], of[f][3]);
  }
  if ((lane & 3) == 0) {
    g_Mpart[split * NTOK + mb + wm + r0] = mrow0;
    g_Lpart[split * NTOK + mb + wm + r0] = l0;
    g_Mpart[split * NTOK + mb + wm + r1] = mrow1;
    g_Lpart[split * NTOK + mb + wm + r1] = l1;
  }
}

// ---------------------------------------------------------------------------
// Kernel 3: split-KV merge.
// ---------------------------------------------------------------------------
__global__ __launch_bounds__(256) void merge_kernel(float* __restrict__ out) {
  const int tid = threadIdx.x;
  const int row = blockIdx.x * 8 + (tid >> 5);
  const int c4 = (tid & 31) * 4;

  float ma = g_Mpart[row], la = g_Lpart[row];
  float mb2 = g_Mpart[NTOK + row], lb = g_Lpart[NTOK + row];
  float M = fmaxf(ma, mb2);
  float wa = ex2f(ma - M), wb = ex2f(mb2 - M);
  float inv = 1.0f / (wa * la + wb * lb);

  float4 oa = *(const float4*)&g_Opart[(size_t)row * DH + c4];
  float4 ob = *(const float4*)&g_Opart[(size_t)(NTOK + row) * DH + c4];
  float4 r;
  r.x = (wa * oa.x + wb * ob.x) * inv;
  r.y = (wa * oa.y + wb * ob.y) * inv;
  r.z = (wa * oa.z + wb * ob.z) * inv;
  r.w = (wa * oa.w + wb * ob.w) * inv;
  *(float4*)&out[(size_t)row * DH + c4] = r;
}

// ---------------------------------------------------------------------------
extern "C" void kernel_launch(void* const* d_in, const int* in_sizes, int n_in,
                              void* d_out, int out_size) {
  const float* x  = (const float*)d_in[0];
  const float* Wq = (const float*)d_in[1];
  const float* Wk = (const float*)d_in[2];
  const float* Wv = (const float*)d_in[3];
  float* out = (float*)d_out;

  split_all_kernel<<<NTOK * DIN / 1024 + 3 * (DIN * DH / 1024), 256>>>(
      x, Wq, Wk, Wv);

  cudaFuncSetAttribute(qkv_proj_mma, cudaFuncAttributeMaxDynamicSharedMemorySize,
                       SMEM_PROJ);
  qkv_proj_mma<<<dim3(NTOK / 64, 3, 1), 128, SMEM_PROJ>>>();

  cudaFuncSetAttribute(flash_mma, cudaFuncAttributeMaxDynamicSharedMemorySize,
                       SMEM_FLASH);
  flash_mma<<<dim3(NTOK / 128, NSPLIT, 1), 256, SMEM_FLASH>>>(0);

  merge_kernel<<<NTOK / 8, 256>>>(out);
}

// round 11
// speedup vs baseline: 1.0377x; 1.0377x over previous
#include <cuda_runtime.h>
#include <cuda_bf16.h>
#include <cuda_fp16.h>
#include <cstdint>

#define NTOK 8192
#define DIN  1024
#define DH   128

// Pre-split inputs (prep kernel).
__device__ __nv_bfloat16 g_Xhi[NTOK * DIN], g_Xlo[NTOK * DIN];
__device__ __nv_bfloat16 g_Whi[3 * DIN * DH], g_Wlo[3 * DIN * DH];
// Split operands produced by the projection kernel.
__device__ __nv_bfloat16 g_Qhi[NTOK * DH], g_Qlo[NTOK * DH]; // pre-scaled by (1/sqrt d)*log2 e
__device__ __nv_bfloat16 g_Khi[NTOK * DH], g_Klo[NTOK * DH];
__device__ __half        g_Vhi[NTOK * DH];

// Flat-scheduled flash partials: 148 CTAs x <=2 segments.
#define NCTA_F 148
#define NSEG (2 * NCTA_F)            // 296
__device__ float g_OpartSeg[NSEG * 128 * DH];
__device__ float g_MsegA[NSEG * 128];
__device__ float g_LsegA[NSEG * 128];
__device__ int   g_SegBlk[NSEG];     // block+1; 0 = empty

__device__ __forceinline__ uint32_t smem_u32(const void* p) {
  uint32_t a;
  asm("{ .reg .u64 t; cvta.to.shared.u64 t, %1; cvt.u32.u64 %0, t; }"
      : "=r"(a) : "l"(p));
  return a;
}
__device__ __forceinline__ float ex2f(float x) {
  float y; asm("ex2.approx.ftz.f32 %0, %1;" : "=f"(y) : "f"(x)); return y;
}
__device__ __forceinline__ void ldsm4(uint32_t* r, uint32_t addr) {
  asm volatile("ldmatrix.sync.aligned.m8n8.x4.shared.b16 {%0,%1,%2,%3}, [%4];"
               : "=r"(r[0]), "=r"(r[1]), "=r"(r[2]), "=r"(r[3]) : "r"(addr));
}
__device__ __forceinline__ void ldsm4t(uint32_t* r, uint32_t addr) {
  asm volatile("ldmatrix.sync.aligned.m8n8.x4.trans.shared.b16 {%0,%1,%2,%3}, [%4];"
               : "=r"(r[0]), "=r"(r[1]), "=r"(r[2]), "=r"(r[3]) : "r"(addr));
}
__device__ __forceinline__ void mma_bf16(float* d, const uint32_t* a,
                                         const uint32_t* b) {
  asm volatile(
      "mma.sync.aligned.m16n8k16.row.col.f32.bf16.bf16.f32 "
      "{%0,%1,%2,%3}, {%4,%5,%6,%7}, {%8,%9}, {%0,%1,%2,%3};"
      : "+f"(d[0]), "+f"(d[1]), "+f"(d[2]), "+f"(d[3])
      : "r"(a[0]), "r"(a[1]), "r"(a[2]), "r"(a[3]), "r"(b[0]), "r"(b[1]));
}
__device__ __forceinline__ void mma_f16(float* d, const uint32_t* a,
                                        const uint32_t* b) {
  asm volatile(
      "mma.sync.aligned.m16n8k16.row.col.f32.f16.f16.f32 "
      "{%0,%1,%2,%3}, {%4,%5,%6,%7}, {%8,%9}, {%0,%1,%2,%3};"
      : "+f"(d[0]), "+f"(d[1]), "+f"(d[2]), "+f"(d[3])
      : "r"(a[0]), "r"(a[1]), "r"(a[2]), "r"(a[3]), "r"(b[0]), "r"(b[1]));
}
__device__ __forceinline__ void cpa16(uint32_t dst, const void* src) {
  asm volatile("cp.async.cg.shared.global [%0], [%1], 16;" :: "r"(dst), "l"(src));
}
#define CP_COMMIT() asm volatile("cp.async.commit_group;" ::: "memory")
#define CP_WAIT1() asm volatile("cp.async.wait_group 1;" ::: "memory")
#define CP_WAIT0() asm volatile("cp.async.wait_group 0;" ::: "memory")

// ---------------------------------------------------------------------------
// Prep kernel: split x and W (fp32 -> bf16 hi/lo) in one launch.
// ---------------------------------------------------------------------------
__global__ __launch_bounds__(256) void split_all_kernel(
    const float* __restrict__ x, const float* __restrict__ Wq,
    const float* __restrict__ Wk, const float* __restrict__ Wv) {
  int b = blockIdx.x;
  const float* src;
  __nv_bfloat16 *dhi, *dlo;
  size_t i;
  float sc = 1.0f;
  if (b < NTOK * DIN / 1024) {
    src = x;  dhi = g_Xhi;  dlo = g_Xlo;
    i = ((size_t)b * 256 + threadIdx.x) * 4;
  } else {
    int w = b - NTOK * DIN / 1024;
    int y = w >> 7, bx = w & 127;
    if (y == 0) { src = Wq; sc = 0.08838834764831845f * 1.4426950408889634f; }
    else if (y == 1) src = Wk;
    else src = Wv;
    i = ((size_t)bx * 256 + threadIdx.x) * 4;
    dhi = g_Whi + (size_t)y * DIN * DH;
    dlo = g_Wlo + (size_t)y * DIN * DH;
  }
  float4 v = *(const float4*)(src + i);
  v.x *= sc; v.y *= sc; v.z *= sc; v.w *= sc;
  __nv_bfloat16 h0 = __float2bfloat16_rn(v.x), h1 = __float2bfloat16_rn(v.y);
  __nv_bfloat16 h2 = __float2bfloat16_rn(v.z), h3 = __float2bfloat16_rn(v.w);
  __nv_bfloat162 hh0 = __halves2bfloat162(h0, h1), hh1 = __halves2bfloat162(h2, h3);
  __nv_bfloat162 ll0 = __halves2bfloat162(
      __float2bfloat16_rn(v.x - __bfloat162float(h0)),
      __float2bfloat16_rn(v.y - __bfloat162float(h1)));
  __nv_bfloat162 ll1 = __halves2bfloat162(
      __float2bfloat16_rn(v.z - __bfloat162float(h2)),
      __float2bfloat16_rn(v.w - __bfloat162float(h3)));
  *(uint2*)&dhi[i] = make_uint2(*(uint32_t*)&hh0, *(uint32_t*)&hh1);
  *(uint2*)&dlo[i] = make_uint2(*(uint32_t*)&ll0, *(uint32_t*)&ll1);
}

// ---------------------------------------------------------------------------
// Kernel 1: QKV projection GEMM, BM=64, 128 threads, 2 CTAs/SM.
// ---------------------------------------------------------------------------
#define XROW 144
#define WROW 272
#define PSTAGE 53248
#define SMEM_PROJ (2 * PSTAGE)

__device__ __forceinline__ void proj_issue(int tid, int mb, int y, int k0,
                                           uint32_t dstbase) {
#pragma unroll
  for (int it = 0; it < 8; it++) {
    int idx = tid + it * 128;
    int arr = idx >> 9, w = idx & 511;
    int r = w >> 3, c = w & 7;
    const __nv_bfloat16* src = (arr ? g_Xlo : g_Xhi) +
                               (size_t)(mb + r) * DIN + k0 + c * 8;
    cpa16(dstbase + arr * 9216 + r * XROW + c * 16, src);
  }
#pragma unroll
  for (int it = 0; it < 16; it++) {
    int idx = tid + it * 128;
    int arr = idx >> 10, w = idx & 1023;
    int r = w >> 4, c = w & 15;
    const __nv_bfloat16* src = (arr ? g_Wlo : g_Whi) +
                               (size_t)y * DIN * DH + (size_t)(k0 + r) * DH + c * 8;
    cpa16(dstbase + 18432 + arr * 17408 + r * WROW + c * 16, src);
  }
}

__global__ __launch_bounds__(128, 2) void qkv_proj_mma() {
  extern __shared__ char smc[];
  const int tid = threadIdx.x;
  const int lane = tid & 31, warp = tid >> 5;
  const int wm = warp * 16;
  const int mb = blockIdx.x * 64;
  const int y = blockIdx.y;
  const uint32_t sb = smem_u32(smc);

  float acc[16][4];
#pragma unroll
  for (int f = 0; f < 16; f++)
#pragma unroll
    for (int e = 0; e < 4; e++) acc[f][e] = 0.f;

  const uint32_t ah_addr = sb + (uint32_t)(wm + (lane & 15)) * XROW +
                           (lane >> 4) * 16;
  const uint32_t bh_addr = sb + 18432 +
                           (uint32_t)((lane & 7) + ((lane >> 3) & 1) * 8) * WROW +
                           ((lane >> 4) & 1) * 16;

  proj_issue(tid, mb, y, 0, sb);           CP_COMMIT();
  proj_issue(tid, mb, y, 64, sb + PSTAGE); CP_COMMIT();

  const int NT = DIN / 64;   // 16
  for (int t = 0; t < NT; t++) {
    if (t + 1 < NT) CP_WAIT1(); else CP_WAIT0();
    __syncthreads();
    uint32_t bo = (uint32_t)(t & 1) * PSTAGE;
#pragma unroll
    for (int j = 0; j < 4; j++) {
      uint32_t ah[4], al[4];
      ldsm4(ah, ah_addr + bo + j * 32);
      ldsm4(al, ah_addr + bo + 9216 + j * 32);
#pragma unroll
      for (int f2 = 0; f2 < 8; f2++) {
        uint32_t bh[4], bl[4];
        uint32_t a = bh_addr + bo + (uint32_t)(j * 16) * WROW + f2 * 32;
        ldsm4t(bh, a);
        ldsm4t(bl, a + 17408);
        mma_bf16(acc[2 * f2], ah, bh);
        mma_bf16(acc[2 * f2 + 1], ah, bh + 2);
        mma_bf16(acc[2 * f2], ah, bl);
        mma_bf16(acc[2 * f2 + 1], ah, bl + 2);
        mma_bf16(acc[2 * f2], al, bh);
        mma_bf16(acc[2 * f2 + 1], al, bh + 2);
      }
    }
    __syncthreads();
    if (t + 2 < NT) { proj_issue(tid, mb, y, (t + 2) * 64, sb + bo); }
    CP_COMMIT();
  }

  int r0 = mb + wm + (lane >> 2), r1 = r0 + 8;
  int cb = 2 * (lane & 3);
#pragma unroll
  for (int f = 0; f < 16; f++) {
    int c = 8 * f + cb;
    float v0 = acc[f][0], v1 = acc[f][1], v2 = acc[f][2], v3 = acc[f][3];
    if (y == 2) {
      *(__half2*)&g_Vhi[(size_t)r0 * DH + c] = __floats2half2_rn(v0, v1);
      *(__half2*)&g_Vhi[(size_t)r1 * DH + c] = __floats2half2_rn(v2, v3);
    } else {
      __nv_bfloat16 h0 = __float2bfloat16_rn(v0), h1 = __float2bfloat16_rn(v1);
      __nv_bfloat16 h2 = __float2bfloat16_rn(v2), h3 = __float2bfloat16_rn(v3);
      __nv_bfloat16* hi = y ? g_Khi : g_Qhi;
      __nv_bfloat16* lo = y ? g_Klo : g_Qlo;
      *(__nv_bfloat162*)&hi[(size_t)r0 * DH + c] = __halves2bfloat162(h0, h1);
      *(__nv_bfloat162*)&hi[(size_t)r1 * DH + c] = __halves2bfloat162(h2, h3);
      *(__nv_bfloat162*)&lo[(size_t)r0 * DH + c] = __halves2bfloat162(
          __float2bfloat16_rn(v0 - __bfloat162float(h0)),
          __float2bfloat16_rn(v1 - __bfloat162float(h1)));
      *(__nv_bfloat162*)&lo[(size_t)r1 * DH + c] = __halves2bfloat162(
          __float2bfloat16_rn(v2 - __bfloat162float(h2)),
          __float2bfloat16_rn(v3 - __bfloat162float(h3)));
    }
  }
}

// ---------------------------------------------------------------------------
// Kernel 2: flash attention, flat-scheduled over 148 CTAs.
// Work = 64 Q-blocks (BM=128) x 128 key-tiles (BN=64) = 8192 flat units.
// CTA i: flat range [i*8192/148, (i+1)*8192/148) -> 55-56 tiles, <=2 segments
// (Q-block changes at most once).  3-stage cp.async ring, Q fragments in
// registers (reloaded per segment), PV = Phi * Vhi (fp16).
// smem: ring 3 x 52224 + Q area 2 x 34816 = 226304 B.
// ---------------------------------------------------------------------------
#define ROWB 272
#define SKLO 17408
#define SVHI 34816
#define FSTAGE 52224
#define QOFF (3 * FSTAGE)
#define SMEM_FLASH (QOFF + 2 * 34816)
#define FTILES 8192

__device__ __forceinline__ void flash_issue(int tid, int n0, uint32_t dstbase) {
#pragma unroll
  for (int it = 0; it < 12; it++) {
    int idx = tid + it * 256;
    int arr = idx >> 10, w = idx & 1023;
    int r = w >> 4, c = w & 15;
    const __nv_bfloat16* srcb;
    if (arr == 0)      srcb = g_Khi;
    else if (arr == 1) srcb = g_Klo;
    else               srcb = (const __nv_bfloat16*)g_Vhi;
    cpa16(dstbase + arr * 17408 + r * ROWB + c * 16,
          srcb + (size_t)(n0 + r) * DH + c * 8);
  }
}

__global__ __launch_bounds__(256, 1) void flash_mma(int dummy) {
  extern __shared__ char smc[];
  const int tid = threadIdx.x;
  const int lane = tid & 31, warp = tid >> 5;
  const int wm = warp * 16;
  const int cta = blockIdx.x;
  const uint32_t sb = smem_u32(smc);

  const int Tstart = (cta * FTILES) / NCTA_F;
  const int Tend = ((cta + 1) * FTILES) / NCTA_F;

  // Prime the ring with the first two tiles (every CTA has >= 55 tiles).
  flash_issue(tid, (Tstart & 127) * 64, sb);                 CP_COMMIT();
  flash_issue(tid, ((Tstart + 1) & 127) * 64, sb + FSTAGE);  CP_COMMIT();

  const uint32_t qfrag_addr = sb + QOFF + (uint32_t)(wm + (lane & 15)) * ROWB +
                              (lane >> 4) * 16;
  const uint32_t kaddr = sb + (uint32_t)((lane & 7) + ((lane >> 4) << 3)) * ROWB +
                         ((lane >> 3) & 1) * 16;
  const uint32_t vaddr = sb + (uint32_t)((lane & 7) + (((lane >> 3) & 1) << 3)) * ROWB +
                         ((lane >> 4) & 1) * 16 + SVHI;

  uint32_t qh[8][4], ql[8][4];
  float of[16][4];
  float mrow0 = -1e30f, mrow1 = -1e30f, l0 = 0.f, l1 = 0.f;
  int curblk = -1, seg = 0;

  const int r0 = lane >> 2, r1 = r0 + 8;
  const int cbase = 2 * (lane & 3);

  for (int t = Tstart; t < Tend; t++) {
    if (t < Tend - 1) CP_WAIT1(); else CP_WAIT0();
    __syncthreads();   // stage (t-Tstart)%3 visible; stage (t+2-Tstart)%3 free
    if (t + 2 < Tend) {
      flash_issue(tid, ((t + 2) & 127) * 64,
                  sb + (uint32_t)((t + 2 - Tstart) % 3) * FSTAGE);
      CP_COMMIT();
    }

    // ---- Q-block boundary: flush previous segment, load new Q ----
    if ((t >> 7) != curblk) {
      if (curblk >= 0) {
        int slot = cta * 2 + seg;
        float* Ob = g_OpartSeg + (size_t)slot * 128 * DH;
        int lr0 = wm + r0, lr1 = wm + r1;
#pragma unroll
        for (int f = 0; f < 16; f++) {
          *(float2*)&Ob[lr0 * DH + 8 * f + cbase] = make_float2(of[f][0], of[f][1]);
          *(float2*)&Ob[lr1 * DH + 8 * f + cbase] = make_float2(of[f][2], of[f][3]);
        }
        if ((lane & 3) == 0) {
          g_MsegA[slot * 128 + lr0] = mrow0;  g_LsegA[slot * 128 + lr0] = l0;
          g_MsegA[slot * 128 + lr1] = mrow1;  g_LsegA[slot * 128 + lr1] = l1;
        }
        if (tid == 0) g_SegBlk[slot] = curblk + 1;
        seg = 1;
      }
      curblk = t >> 7;
      // Stage Q for this block into the dedicated area.
#pragma unroll
      for (int it = 0; it < 8; it++) {
        int idx = tid + it * 256;
        int r = idx >> 4, c = idx & 15;
        size_t g = (size_t)(curblk * 128 + r) * DH + c * 8;
        *(float4*)(smc + QOFF + r * ROWB + c * 16) = *(const float4*)(g_Qhi + g);
        *(float4*)(smc + QOFF + 34816 + r * ROWB + c * 16) =
            *(const float4*)(g_Qlo + g);
      }
      __syncthreads();
#pragma unroll
      for (int j = 0; j < 8; j++) {
        ldsm4(qh[j], qfrag_addr + j * 32);
        ldsm4(ql[j], qfrag_addr + 34816 + j * 32);
      }
#pragma unroll
      for (int f = 0; f < 16; f++)
#pragma unroll
        for (int e = 0; e < 4; e++) of[f][e] = 0.f;
      mrow0 = -1e30f; mrow1 = -1e30f; l0 = 0.f; l1 = 0.f;
    }

    const uint32_t bo = (uint32_t)((t - Tstart) % 3) * FSTAGE;

    // ---- S = Q K^T ----
    float sf[8][4];
#pragma unroll
    for (int f = 0; f < 8; f++)
#pragma unroll
      for (int e = 0; e < 4; e++) sf[f][e] = 0.f;
#pragma unroll
    for (int j = 0; j < 8; j++) {
#pragma unroll
      for (int f2 = 0; f2 < 4; f2++) {
        uint32_t bh[4], bl[4];
        uint32_t a = kaddr + bo + (uint32_t)(f2 * 16) * ROWB + j * 32;
        ldsm4(bh, a);
        ldsm4(bl, a + SKLO);
        mma_bf16(sf[2 * f2], qh[j], bh);
        mma_bf16(sf[2 * f2 + 1], qh[j], bh + 2);
        mma_bf16(sf[2 * f2], qh[j], bl);
        mma_bf16(sf[2 * f2 + 1], qh[j], bl + 2);
        mma_bf16(sf[2 * f2], ql[j], bh);
        mma_bf16(sf[2 * f2 + 1], ql[j], bh + 2);
      }
    }

    // ---- online softmax (base-2 logits) ----
    float mx0 = sf[0][0], mx1 = sf[0][2];
#pragma unroll
    for (int f = 0; f < 8; f++) {
      mx0 = fmaxf(mx0, fmaxf(sf[f][0], sf[f][1]));
      mx1 = fmaxf(mx1, fmaxf(sf[f][2], sf[f][3]));
    }
    mx0 = fmaxf(mx0, __shfl_xor_sync(0xffffffffu, mx0, 1));
    mx0 = fmaxf(mx0, __shfl_xor_sync(0xffffffffu, mx0, 2));
    mx1 = fmaxf(mx1, __shfl_xor_sync(0xffffffffu, mx1, 1));
    mx1 = fmaxf(mx1, __shfl_xor_sync(0xffffffffu, mx1, 2));

    float mn0 = fmaxf(mrow0, mx0), mn1 = fmaxf(mrow1, mx1);
    float a0 = ex2f(mrow0 - mn0), a1 = ex2f(mrow1 - mn1);
    mrow0 = mn0; mrow1 = mn1;

    float s0 = 0.f, s1 = 0.f;
#pragma unroll
    for (int f = 0; f < 8; f++) {
      sf[f][0] = ex2f(sf[f][0] - mn0);
      sf[f][1] = ex2f(sf[f][1] - mn0);
      sf[f][2] = ex2f(sf[f][2] - mn1);
      sf[f][3] = ex2f(sf[f][3] - mn1);
      s0 += sf[f][0] + sf[f][1];
      s1 += sf[f][2] + sf[f][3];
    }
    s0 += __shfl_xor_sync(0xffffffffu, s0, 1);
    s0 += __shfl_xor_sync(0xffffffffu, s0, 2);
    s1 += __shfl_xor_sync(0xffffffffu, s1, 1);
    s1 += __shfl_xor_sync(0xffffffffu, s1, 2);
    l0 = l0 * a0 + s0;
    l1 = l1 * a1 + s1;

    if (!__all_sync(0xffffffffu, (__float_as_uint(a0) == 0x3f800000u) &&
                                (__float_as_uint(a1) == 0x3f800000u))) {
#pragma unroll
      for (int f = 0; f < 16; f++) {
        of[f][0] *= a0;  of[f][1] *= a0;
        of[f][2] *= a1;  of[f][3] *= a1;
      }
    }

    // ---- O += P V ----
#pragma unroll
    for (int j2 = 0; j2 < 4; j2++) {
      uint32_t ph[4];
      __half2 h;
      h = __floats2half2_rn(sf[2 * j2][0], sf[2 * j2][1]);         ph[0] = *(uint32_t*)&h;
      h = __floats2half2_rn(sf[2 * j2][2], sf[2 * j2][3]);         ph[1] = *(uint32_t*)&h;
      h = __floats2half2_rn(sf[2 * j2 + 1][0], sf[2 * j2 + 1][1]); ph[2] = *(uint32_t*)&h;
      h = __floats2half2_rn(sf[2 * j2 + 1][2], sf[2 * j2 + 1][3]); ph[3] = *(uint32_t*)&h;
      uint32_t ka = vaddr + bo + (uint32_t)(j2 * 16) * ROWB;
#pragma unroll
      for (int f2 = 0; f2 < 8; f2++) {
        uint32_t bv[4];
        ldsm4t(bv, ka + f2 * 32);
        mma_f16(of[2 * f2], ph, bv);
        mma_f16(of[2 * f2 + 1], ph, bv + 2);
      }
    }
  }

  // ---- flush final segment ----
  {
    int slot = cta * 2 + seg;
    float* Ob = g_OpartSeg + (size_t)slot * 128 * DH;
    int lr0 = wm + r0, lr1 = wm + r1;
#pragma unroll
    for (int f = 0; f < 16; f++) {
      *(float2*)&Ob[lr0 * DH + 8 * f + cbase] = make_float2(of[f][0], of[f][1]);
      *(float2*)&Ob[lr1 * DH + 8 * f + cbase] = make_float2(of[f][2], of[f][3]);
    }
    if ((lane & 3) == 0) {
      g_MsegA[slot * 128 + lr0] = mrow0;  g_LsegA[slot * 128 + lr0] = l0;
      g_MsegA[slot * 128 + lr1] = mrow1;  g_LsegA[slot * 128 + lr1] = l1;
    }
    if (tid == 0) g_SegBlk[slot] = curblk + 1;
  }
}

// ---------------------------------------------------------------------------
// Kernel 3: merge variable segment partials per Q-block.
// grid = 1024 blocks x 256 thr; 8 rows per block (all in one Q-block).
// ---------------------------------------------------------------------------
__global__ __launch_bounds__(256) void merge_kernel(float* __restrict__ out) {
  __shared__ unsigned char flags[NSEG];
  __shared__ int slots[8];
  __shared__ int nseg;
  const int tid = threadIdx.x;
  const int row0 = blockIdx.x * 8;
  const int qblk = row0 >> 7;

  for (int s = tid; s < NSEG; s += 256)
    flags[s] = (g_SegBlk[s] == qblk + 1);
  __syncthreads();
  if (tid == 0) {
    int n = 0;
    for (int s = 0; s < NSEG; s++)
      if (flags[s] && n < 8) slots[n++] = s;
    nseg = n;
  }
  __syncthreads();

  const int row = row0 + (tid >> 5);
  const int lrow = row & 127;
  const int c4 = (tid & 31) * 4;

  float m = -1e30f, l = 0.f;
  float4 O = make_float4(0.f, 0.f, 0.f, 0.f);
  int n = nseg;
  for (int i = 0; i < n; i++) {
    int s = slots[i];
    float ms = g_MsegA[s * 128 + lrow];
    float ls = g_LsegA[s * 128 + lrow];
    float4 Os = *(const float4*)&g_OpartSeg[(size_t)s * 128 * DH + lrow * DH + c4];
    float mn = fmaxf(m, ms);
    float wa = ex2f(m - mn), wb = ex2f(ms - mn);
    O.x = O.x * wa + Os.x * wb;
    O.y = O.y * wa + Os.y * wb;
    O.z = O.z * wa + Os.z * wb;
    O.w = O.w * wa + Os.w * wb;
    l = l * wa + ls * wb;
    m = mn;
  }
  float inv = 1.0f / l;
  float4 r = make_float4(O.x * inv, O.y * inv, O.z * inv, O.w * inv);
  *(float4*)&out[(size_t)row * DH + c4] = r;
}

// ---------------------------------------------------------------------------
extern "C" void kernel_launch(void* const* d_in, const int* in_sizes, int n_in,
                              void* d_out, int out_size) {
  const float* x  = (const float*)d_in[0];
  const float* Wq = (const float*)d_in[1];
  const float* Wk = (const float*)d_in[2];
  const float* Wv = (const float*)d_in[3];
  float* out = (float*)d_out;

  split_all_kernel<<<NTOK * DIN / 1024 + 3 * (DIN * DH / 1024), 256>>>(
      x, Wq, Wk, Wv);

  cudaFuncSetAttribute(qkv_proj_mma, cudaFuncAttributeMaxDynamicSharedMemorySize,
                       SMEM_PROJ);
  qkv_proj_mma<<<dim3(NTOK / 64, 3, 1), 128, SMEM_PROJ>>>();

  cudaFuncSetAttribute(flash_mma, cudaFuncAttributeMaxDynamicSharedMemorySize,
                       SMEM_FLASH);
  flash_mma<<<NCTA_F, 256, SMEM_FLASH>>>(0);

  merge_kernel<<<NTOK / 8, 256>>>(out);
}

// round 12
// speedup vs baseline: 1.0682x; 1.0294x over previous
#include <cuda_runtime.h>
#include <cuda_bf16.h>
#include <cuda_fp16.h>
#include <cstdint>

#define NTOK 8192
#define DIN  1024
#define DH   128

// Pre-split inputs (prep kernel).
__device__ __nv_bfloat16 g_Xhi[NTOK * DIN], g_Xlo[NTOK * DIN];
__device__ __nv_bfloat16 g_Whi[3 * DIN * DH], g_Wlo[3 * DIN * DH];
// Split operands produced by the projection kernel.
__device__ __nv_bfloat16 g_Qhi[NTOK * DH], g_Qlo[NTOK * DH]; // pre-scaled by (1/sqrt d)*log2 e
__device__ __nv_bfloat16 g_Khi[NTOK * DH], g_Klo[NTOK * DH];
__device__ __half        g_Vhi[NTOK * DH];

// Flat-scheduled flash partials: 148 CTAs x <=2 segments (slot = 2*cta + seg).
#define NCTA_F 148
#define NSEG (2 * NCTA_F)            // 296
#define FTILES 8192
__device__ float g_OpartSeg[NSEG * 128 * DH];
__device__ float g_MsegA[NSEG * 128];
__device__ float g_LsegA[NSEG * 128];

__device__ __forceinline__ uint32_t smem_u32(const void* p) {
  uint32_t a;
  asm("{ .reg .u64 t; cvta.to.shared.u64 t, %1; cvt.u32.u64 %0, t; }"
      : "=r"(a) : "l"(p));
  return a;
}
__device__ __forceinline__ float ex2f(float x) {
  float y; asm("ex2.approx.ftz.f32 %0, %1;" : "=f"(y) : "f"(x)); return y;
}
__device__ __forceinline__ void ldsm4(uint32_t* r, uint32_t addr) {
  asm volatile("ldmatrix.sync.aligned.m8n8.x4.shared.b16 {%0,%1,%2,%3}, [%4];"
               : "=r"(r[0]), "=r"(r[1]), "=r"(r[2]), "=r"(r[3]) : "r"(addr));
}
__device__ __forceinline__ void ldsm4t(uint32_t* r, uint32_t addr) {
  asm volatile("ldmatrix.sync.aligned.m8n8.x4.trans.shared.b16 {%0,%1,%2,%3}, [%4];"
               : "=r"(r[0]), "=r"(r[1]), "=r"(r[2]), "=r"(r[3]) : "r"(addr));
}
__device__ __forceinline__ void mma_bf16(float* d, const uint32_t* a,
                                         const uint32_t* b) {
  asm volatile(
      "mma.sync.aligned.m16n8k16.row.col.f32.bf16.bf16.f32 "
      "{%0,%1,%2,%3}, {%4,%5,%6,%7}, {%8,%9}, {%0,%1,%2,%3};"
      : "+f"(d[0]), "+f"(d[1]), "+f"(d[2]), "+f"(d[3])
      : "r"(a[0]), "r"(a[1]), "r"(a[2]), "r"(a[3]), "r"(b[0]), "r"(b[1]));
}
__device__ __forceinline__ void mma_f16(float* d, const uint32_t* a,
                                        const uint32_t* b) {
  asm volatile(
      "mma.sync.aligned.m16n8k16.row.col.f32.f16.f16.f32 "
      "{%0,%1,%2,%3}, {%4,%5,%6,%7}, {%8,%9}, {%0,%1,%2,%3};"
      : "+f"(d[0]), "+f"(d[1]), "+f"(d[2]), "+f"(d[3])
      : "r"(a[0]), "r"(a[1]), "r"(a[2]), "r"(a[3]), "r"(b[0]), "r"(b[1]));
}
__device__ __forceinline__ void cpa16(uint32_t dst, const void* src) {
  asm volatile("cp.async.cg.shared.global [%0], [%1], 16;" :: "r"(dst), "l"(src));
}
#define CP_COMMIT() asm volatile("cp.async.commit_group;" ::: "memory")
#define CP_WAIT1() asm volatile("cp.async.wait_group 1;" ::: "memory")
#define CP_WAIT0() asm volatile("cp.async.wait_group 0;" ::: "memory")

// ---------------------------------------------------------------------------
// Prep kernel: split x and W (fp32 -> bf16 hi/lo) in one launch.
// ---------------------------------------------------------------------------
__global__ __launch_bounds__(256) void split_all_kernel(
    const float* __restrict__ x, const float* __restrict__ Wq,
    const float* __restrict__ Wk, const float* __restrict__ Wv) {
  int b = blockIdx.x;
  const float* src;
  __nv_bfloat16 *dhi, *dlo;
  size_t i;
  float sc = 1.0f;
  if (b < NTOK * DIN / 1024) {
    src = x;  dhi = g_Xhi;  dlo = g_Xlo;
    i = ((size_t)b * 256 + threadIdx.x) * 4;
  } else {
    int w = b - NTOK * DIN / 1024;
    int y = w >> 7, bx = w & 127;
    if (y == 0) { src = Wq; sc = 0.08838834764831845f * 1.4426950408889634f; }
    else if (y == 1) src = Wk;
    else src = Wv;
    i = ((size_t)bx * 256 + threadIdx.x) * 4;
    dhi = g_Whi + (size_t)y * DIN * DH;
    dlo = g_Wlo + (size_t)y * DIN * DH;
  }
  float4 v = *(const float4*)(src + i);
  v.x *= sc; v.y *= sc; v.z *= sc; v.w *= sc;
  __nv_bfloat16 h0 = __float2bfloat16_rn(v.x), h1 = __float2bfloat16_rn(v.y);
  __nv_bfloat16 h2 = __float2bfloat16_rn(v.z), h3 = __float2bfloat16_rn(v.w);
  __nv_bfloat162 hh0 = __halves2bfloat162(h0, h1), hh1 = __halves2bfloat162(h2, h3);
  __nv_bfloat162 ll0 = __halves2bfloat162(
      __float2bfloat16_rn(v.x - __bfloat162float(h0)),
      __float2bfloat16_rn(v.y - __bfloat162float(h1)));
  __nv_bfloat162 ll1 = __halves2bfloat162(
      __float2bfloat16_rn(v.z - __bfloat162float(h2)),
      __float2bfloat16_rn(v.w - __bfloat162float(h3)));
  *(uint2*)&dhi[i] = make_uint2(*(uint32_t*)&hh0, *(uint32_t*)&hh1);
  *(uint2*)&dlo[i] = make_uint2(*(uint32_t*)&ll0, *(uint32_t*)&ll1);
}

// ---------------------------------------------------------------------------
// Kernel 1: QKV projection GEMM, BM=64, 128 threads, 2 CTAs/SM.
// ---------------------------------------------------------------------------
#define XROW 144
#define WROW 272
#define PSTAGE 53248
#define SMEM_PROJ (2 * PSTAGE)

__device__ __forceinline__ void proj_issue(int tid, int mb, int y, int k0,
                                           uint32_t dstbase) {
#pragma unroll
  for (int it = 0; it < 8; it++) {
    int idx = tid + it * 128;
    int arr = idx >> 9, w = idx & 511;
    int r = w >> 3, c = w & 7;
    const __nv_bfloat16* src = (arr ? g_Xlo : g_Xhi) +
                               (size_t)(mb + r) * DIN + k0 + c * 8;
    cpa16(dstbase + arr * 9216 + r * XROW + c * 16, src);
  }
#pragma unroll
  for (int it = 0; it < 16; it++) {
    int idx = tid + it * 128;
    int arr = idx >> 10, w = idx & 1023;
    int r = w >> 4, c = w & 15;
    const __nv_bfloat16* src = (arr ? g_Wlo : g_Whi) +
                               (size_t)y * DIN * DH + (size_t)(k0 + r) * DH + c * 8;
    cpa16(dstbase + 18432 + arr * 17408 + r * WROW + c * 16, src);
  }
}

__global__ __launch_bounds__(128, 2) void qkv_proj_mma() {
  extern __shared__ char smc[];
  const int tid = threadIdx.x;
  const int lane = tid & 31, warp = tid >> 5;
  const int wm = warp * 16;
  const int mb = blockIdx.x * 64;
  const int y = blockIdx.y;
  const uint32_t sb = smem_u32(smc);

  float acc[16][4];
#pragma unroll
  for (int f = 0; f < 16; f++)
#pragma unroll
    for (int e = 0; e < 4; e++) acc[f][e] = 0.f;

  const uint32_t ah_addr = sb + (uint32_t)(wm + (lane & 15)) * XROW +
                           (lane >> 4) * 16;
  const uint32_t bh_addr = sb + 18432 +
                           (uint32_t)((lane & 7) + ((lane >> 3) & 1) * 8) * WROW +
                           ((lane >> 4) & 1) * 16;

  proj_issue(tid, mb, y, 0, sb);           CP_COMMIT();
  proj_issue(tid, mb, y, 64, sb + PSTAGE); CP_COMMIT();

  const int NT = DIN / 64;   // 16
  for (int t = 0; t < NT; t++) {
    if (t + 1 < NT) CP_WAIT1(); else CP_WAIT0();
    __syncthreads();
    uint32_t bo = (uint32_t)(t & 1) * PSTAGE;
#pragma unroll
    for (int j = 0; j < 4; j++) {
      uint32_t ah[4], al[4];
      ldsm4(ah, ah_addr + bo + j * 32);
      ldsm4(al, ah_addr + bo + 9216 + j * 32);
#pragma unroll
      for (int f2 = 0; f2 < 8; f2++) {
        uint32_t bh[4], bl[4];
        uint32_t a = bh_addr + bo + (uint32_t)(j * 16) * WROW + f2 * 32;
        ldsm4t(bh, a);
        ldsm4t(bl, a + 17408);
        mma_bf16(acc[2 * f2], ah, bh);
        mma_bf16(acc[2 * f2 + 1], ah, bh + 2);
        mma_bf16(acc[2 * f2], ah, bl);
        mma_bf16(acc[2 * f2 + 1], ah, bl + 2);
        mma_bf16(acc[2 * f2], al, bh);
        mma_bf16(acc[2 * f2 + 1], al, bh + 2);
      }
    }
    __syncthreads();
    if (t + 2 < NT) { proj_issue(tid, mb, y, (t + 2) * 64, sb + bo); }
    CP_COMMIT();
  }

  int r0 = mb + wm + (lane >> 2), r1 = r0 + 8;
  int cb = 2 * (lane & 3);
#pragma unroll
  for (int f = 0; f < 16; f++) {
    int c = 8 * f + cb;
    float v0 = acc[f][0], v1 = acc[f][1], v2 = acc[f][2], v3 = acc[f][3];
    if (y == 2) {
      *(__half2*)&g_Vhi[(size_t)r0 * DH + c] = __floats2half2_rn(v0, v1);
      *(__half2*)&g_Vhi[(size_t)r1 * DH + c] = __floats2half2_rn(v2, v3);
    } else {
      __nv_bfloat16 h0 = __float2bfloat16_rn(v0), h1 = __float2bfloat16_rn(v1);
      __nv_bfloat16 h2 = __float2bfloat16_rn(v2), h3 = __float2bfloat16_rn(v3);
      __nv_bfloat16* hi = y ? g_Khi : g_Qhi;
      __nv_bfloat16* lo = y ? g_Klo : g_Qlo;
      *(__nv_bfloat162*)&hi[(size_t)r0 * DH + c] = __halves2bfloat162(h0, h1);
      *(__nv_bfloat162*)&hi[(size_t)r1 * DH + c] = __halves2bfloat162(h2, h3);
      *(__nv_bfloat162*)&lo[(size_t)r0 * DH + c] = __halves2bfloat162(
          __float2bfloat16_rn(v0 - __bfloat162float(h0)),
          __float2bfloat16_rn(v1 - __bfloat162float(h1)));
      *(__nv_bfloat162*)&lo[(size_t)r1 * DH + c] = __halves2bfloat162(
          __float2bfloat16_rn(v2 - __bfloat162float(h2)),
          __float2bfloat16_rn(v3 - __bfloat162float(h3)));
    }
  }
}

// ---------------------------------------------------------------------------
// Kernel 2: flash attention, flat-scheduled over 148 CTAs.
// CTA i: flat tile range [i*8192/148, (i+1)*8192/148); <=2 Q-block segments.
// Partial for segment s of CTA i goes to slot 2*i+s (implicit; no table).
// ---------------------------------------------------------------------------
#define ROWB 272
#define SKLO 17408
#define SVHI 34816
#define FSTAGE 52224
#define QOFF (3 * FSTAGE)
#define SMEM_FLASH (QOFF + 2 * 34816)

__device__ __forceinline__ void flash_issue(int tid, int n0, uint32_t dstbase) {
#pragma unroll
  for (int it = 0; it < 12; it++) {
    int idx = tid + it * 256;
    int arr = idx >> 10, w = idx & 1023;
    int r = w >> 4, c = w & 15;
    const __nv_bfloat16* srcb;
    if (arr == 0)      srcb = g_Khi;
    else if (arr == 1) srcb = g_Klo;
    else               srcb = (const __nv_bfloat16*)g_Vhi;
    cpa16(dstbase + arr * 17408 + r * ROWB + c * 16,
          srcb + (size_t)(n0 + r) * DH + c * 8);
  }
}

__global__ __launch_bounds__(256, 1) void flash_mma(int dummy) {
  extern __shared__ char smc[];
  const int tid = threadIdx.x;
  const int lane = tid & 31, warp = tid >> 5;
  const int wm = warp * 16;
  const int cta = blockIdx.x;
  const uint32_t sb = smem_u32(smc);

  const int Tstart = (cta * FTILES) / NCTA_F;
  const int Tend = ((cta + 1) * FTILES) / NCTA_F;

  flash_issue(tid, (Tstart & 127) * 64, sb);                 CP_COMMIT();
  flash_issue(tid, ((Tstart + 1) & 127) * 64, sb + FSTAGE);  CP_COMMIT();

  const uint32_t qfrag_addr = sb + QOFF + (uint32_t)(wm + (lane & 15)) * ROWB +
                              (lane >> 4) * 16;
  const uint32_t kaddr = sb + (uint32_t)((lane & 7) + ((lane >> 4) << 3)) * ROWB +
                         ((lane >> 3) & 1) * 16;
  const uint32_t vaddr = sb + (uint32_t)((lane & 7) + (((lane >> 3) & 1) << 3)) * ROWB +
                         ((lane >> 4) & 1) * 16 + SVHI;

  uint32_t qh[8][4], ql[8][4];
  float of[16][4];
  float mrow0 = -1e30f, mrow1 = -1e30f, l0 = 0.f, l1 = 0.f;
  int curblk = -1, seg = 0;

  const int r0 = lane >> 2, r1 = r0 + 8;
  const int cbase = 2 * (lane & 3);

  for (int t = Tstart; t < Tend; t++) {
    if (t < Tend - 1) CP_WAIT1(); else CP_WAIT0();
    __syncthreads();
    if (t + 2 < Tend) {
      flash_issue(tid, ((t + 2) & 127) * 64,
                  sb + (uint32_t)((t + 2 - Tstart) % 3) * FSTAGE);
      CP_COMMIT();
    }

    // ---- Q-block boundary: flush previous segment, load new Q ----
    if ((t >> 7) != curblk) {
      if (curblk >= 0) {
        int slot = cta * 2 + seg;
        float* Ob = g_OpartSeg + (size_t)slot * 128 * DH;
        int lr0 = wm + r0, lr1 = wm + r1;
#pragma unroll
        for (int f = 0; f < 16; f++) {
          *(float2*)&Ob[lr0 * DH + 8 * f + cbase] = make_float2(of[f][0], of[f][1]);
          *(float2*)&Ob[lr1 * DH + 8 * f + cbase] = make_float2(of[f][2], of[f][3]);
        }
        if ((lane & 3) == 0) {
          g_MsegA[slot * 128 + lr0] = mrow0;  g_LsegA[slot * 128 + lr0] = l0;
          g_MsegA[slot * 128 + lr1] = mrow1;  g_LsegA[slot * 128 + lr1] = l1;
        }
        seg = 1;
      }
      curblk = t >> 7;
#pragma unroll
      for (int it = 0; it < 8; it++) {
        int idx = tid + it * 256;
        int r = idx >> 4, c = idx & 15;
        size_t g = (size_t)(curblk * 128 + r) * DH + c * 8;
        *(float4*)(smc + QOFF + r * ROWB + c * 16) = *(const float4*)(g_Qhi + g);
        *(float4*)(smc + QOFF + 34816 + r * ROWB + c * 16) =
            *(const float4*)(g_Qlo + g);
      }
      __syncthreads();
#pragma unroll
      for (int j = 0; j < 8; j++) {
        ldsm4(qh[j], qfrag_addr + j * 32);
        ldsm4(ql[j], qfrag_addr + 34816 + j * 32);
      }
#pragma unroll
      for (int f = 0; f < 16; f++)
#pragma unroll
        for (int e = 0; e < 4; e++) of[f][e] = 0.f;
      mrow0 = -1e30f; mrow1 = -1e30f; l0 = 0.f; l1 = 0.f;
    }

    const uint32_t bo = (uint32_t)((t - Tstart) % 3) * FSTAGE;

    // ---- S = Q K^T ----
    float sf[8][4];
#pragma unroll
    for (int f = 0; f < 8; f++)
#pragma unroll
      for (int e = 0; e < 4; e++) sf[f][e] = 0.f;
#pragma unroll
    for (int j = 0; j < 8; j++) {
#pragma unroll
      for (int f2 = 0; f2 < 4; f2++) {
        uint32_t bh[4], bl[4];
        uint32_t a = kaddr + bo + (uint32_t)(f2 * 16) * ROWB + j * 32;
        ldsm4(bh, a);
        ldsm4(bl, a + SKLO);
        mma_bf16(sf[2 * f2], qh[j], bh);
        mma_bf16(sf[2 * f2 + 1], qh[j], bh + 2);
        mma_bf16(sf[2 * f2], qh[j], bl);
        mma_bf16(sf[2 * f2 + 1], qh[j], bl + 2);
        mma_bf16(sf[2 * f2], ql[j], bh);
        mma_bf16(sf[2 * f2 + 1], ql[j], bh + 2);
      }
    }

    // ---- online softmax (base-2 logits) ----
    float mx0 = sf[0][0], mx1 = sf[0][2];
#pragma unroll
    for (int f = 0; f < 8; f++) {
      mx0 = fmaxf(mx0, fmaxf(sf[f][0], sf[f][1]));
      mx1 = fmaxf(mx1, fmaxf(sf[f][2], sf[f][3]));
    }
    mx0 = fmaxf(mx0, __shfl_xor_sync(0xffffffffu, mx0, 1));
    mx0 = fmaxf(mx0, __shfl_xor_sync(0xffffffffu, mx0, 2));
    mx1 = fmaxf(mx1, __shfl_xor_sync(0xffffffffu, mx1, 1));
    mx1 = fmaxf(mx1, __shfl_xor_sync(0xffffffffu, mx1, 2));

    float mn0 = fmaxf(mrow0, mx0), mn1 = fmaxf(mrow1, mx1);
    float a0 = ex2f(mrow0 - mn0), a1 = ex2f(mrow1 - mn1);
    mrow0 = mn0; mrow1 = mn1;

    float s0 = 0.f, s1 = 0.f;
#pragma unroll
    for (int f = 0; f < 8; f++) {
      sf[f][0] = ex2f(sf[f][0] - mn0);
      sf[f][1] = ex2f(sf[f][1] - mn0);
      sf[f][2] = ex2f(sf[f][2] - mn1);
      sf[f][3] = ex2f(sf[f][3] - mn1);
      s0 += sf[f][0] + sf[f][1];
      s1 += sf[f][2] + sf[f][3];
    }
    s0 += __shfl_xor_sync(0xffffffffu, s0, 1);
    s0 += __shfl_xor_sync(0xffffffffu, s0, 2);
    s1 += __shfl_xor_sync(0xffffffffu, s1, 1);
    s1 += __shfl_xor_sync(0xffffffffu, s1, 2);
    l0 = l0 * a0 + s0;
    l1 = l1 * a1 + s1;

    if (!__all_sync(0xffffffffu, (__float_as_uint(a0) == 0x3f800000u) &&
                                (__float_as_uint(a1) == 0x3f800000u))) {
#pragma unroll
      for (int f = 0; f < 16; f++) {
        of[f][0] *= a0;  of[f][1] *= a0;
        of[f][2] *= a1;  of[f][3] *= a1;
      }
    }

    // ---- O += P V ----
#pragma unroll
    for (int j2 = 0; j2 < 4; j2++) {
      uint32_t ph[4];
      __half2 h;
      h = __floats2half2_rn(sf[2 * j2][0], sf[2 * j2][1]);         ph[0] = *(uint32_t*)&h;
      h = __floats2half2_rn(sf[2 * j2][2], sf[2 * j2][3]);         ph[1] = *(uint32_t*)&h;
      h = __floats2half2_rn(sf[2 * j2 + 1][0], sf[2 * j2 + 1][1]); ph[2] = *(uint32_t*)&h;
      h = __floats2half2_rn(sf[2 * j2 + 1][2], sf[2 * j2 + 1][3]); ph[3] = *(uint32_t*)&h;
      uint32_t ka = vaddr + bo + (uint32_t)(j2 * 16) * ROWB;
#pragma unroll
      for (int f2 = 0; f2 < 8; f2++) {
        uint32_t bv[4];
        ldsm4t(bv, ka + f2 * 32);
        mma_f16(of[2 * f2], ph, bv);
        mma_f16(of[2 * f2 + 1], ph, bv + 2);
      }
    }
  }

  // ---- flush final segment ----
  {
    int slot = cta * 2 + seg;
    float* Ob = g_OpartSeg + (size_t)slot * 128 * DH;
    int lr0 = wm + r0, lr1 = wm + r1;
#pragma unroll
    for (int f = 0; f < 16; f++) {
      *(float2*)&Ob[lr0 * DH + 8 * f + cbase] = make_float2(of[f][0], of[f][1]);
      *(float2*)&Ob[lr1 * DH + 8 * f + cbase] = make_float2(of[f][2], of[f][3]);
    }
    if ((lane & 3) == 0) {
      g_MsegA[slot * 128 + lr0] = mrow0;  g_LsegA[slot * 128 + lr0] = l0;
      g_MsegA[slot * 128 + lr1] = mrow1;  g_LsegA[slot * 128 + lr1] = l1;
    }
  }
}

// ---------------------------------------------------------------------------
// Kernel 3: merge — ANALYTIC slot enumeration (no table, no scan).
// Q-block q is covered by CTAs i whose tile range intersects [q*128, q*128+128).
// Segment index within CTA i: 0 if q is CTA i's first block, else 1.
// ---------------------------------------------------------------------------
__global__ __launch_bounds__(256) void merge_kernel(float* __restrict__ out) {
  const int tid = threadIdx.x;
  const int row = blockIdx.x * 8 + (tid >> 5);
  const int q = row >> 7;
  const int lrow = row & 127;
  const int c4 = (tid & 31) * 4;

  const int t0 = q * 128, t1 = t0 + 128;

  float m = -1e30f, l = 0.f;
  float4 O = make_float4(0.f, 0.f, 0.f, 0.f);

  int i = (t0 * NCTA_F) / FTILES;   // Tstart(i) <= t0 < Tend(i) guaranteed
#pragma unroll 1
  for (; i < NCTA_F; i++) {
    int ts = (i * FTILES) / NCTA_F;
    if (ts >= t1) break;
    int te = ((i + 1) * FTILES) / NCTA_F;
    if (te <= t0) continue;
    int slot = 2 * i + (((ts >> 7) == q) ? 0 : 1);

    float ms = g_MsegA[slot * 128 + lrow];
    float ls = g_LsegA[slot * 128 + lrow];
    float4 Os = *(const float4*)&g_OpartSeg[(size_t)slot * 128 * DH +
                                            lrow * DH + c4];
    float mn = fmaxf(m, ms);
    float wa = ex2f(m - mn), wb = ex2f(ms - mn);
    O.x = O.x * wa + Os.x * wb;
    O.y = O.y * wa + Os.y * wb;
    O.z = O.z * wa + Os.z * wb;
    O.w = O.w * wa + Os.w * wb;
    l = l * wa + ls * wb;
    m = mn;
  }

  float inv = 1.0f / l;
  float4 r = make_float4(O.x * inv, O.y * inv, O.z * inv, O.w * inv);
  *(float4*)&out[(size_t)row * DH + c4] = r;
}

// ---------------------------------------------------------------------------
extern "C" void kernel_launch(void* const* d_in, const int* in_sizes, int n_in,
                              void* d_out, int out_size) {
  const float* x  = (const float*)d_in[0];
  const float* Wq = (const float*)d_in[1];
  const float* Wk = (const float*)d_in[2];
  const float* Wv = (const float*)d_in[3];
  float* out = (float*)d_out;

  split_all_kernel<<<NTOK * DIN / 1024 + 3 * (DIN * DH / 1024), 256>>>(
      x, Wq, Wk, Wv);

  cudaFuncSetAttribute(qkv_proj_mma, cudaFuncAttributeMaxDynamicSharedMemorySize,
                       SMEM_PROJ);
  qkv_proj_mma<<<dim3(NTOK / 64, 3, 1), 128, SMEM_PROJ>>>();

  cudaFuncSetAttribute(flash_mma, cudaFuncAttributeMaxDynamicSharedMemorySize,
                       SMEM_FLASH);
  flash_mma<<<NCTA_F, 256, SMEM_FLASH>>>(0);

  merge_kernel<<<NTOK / 8, 256>>>(out);
}

// round 13
// speedup vs baseline: 1.1001x; 1.0298x over previous
#include <cuda_runtime.h>
#include <cuda_bf16.h>
#include <cuda_fp16.h>
#include <cstdint>

#define NTOK 8192
#define DIN  1024
#define DH   128

// Pre-split inputs (prep kernel).
__device__ __nv_bfloat16 g_Xhi[NTOK * DIN], g_Xlo[NTOK * DIN];
__device__ __nv_bfloat16 g_Whi[3 * DIN * DH], g_Wlo[3 * DIN * DH];
// Split operands produced by the projection kernel.
__device__ __nv_bfloat16 g_Qhi[NTOK * DH], g_Qlo[NTOK * DH]; // pre-scaled by (1/sqrt d)*log2 e
__device__ __nv_bfloat16 g_Khi[NTOK * DH], g_Klo[NTOK * DH];
__device__ __half        g_Vhi[NTOK * DH];

// Flat-scheduled flash partials: 148 CTAs x <=2 segments (slot = 2*cta + seg).
#define NCTA_F 148
#define NSEG (2 * NCTA_F)            // 296
#define BMF 192                       // rows per Q-block (12 warps x 16)
#define NQB 43                        // ceil(8192 / 192)
#define FTILES (NQB * 128)            // 5504 flat (Q-block, key-tile) units
__device__ float g_OpartSeg[NSEG * BMF * DH];
__device__ float g_MsegA[NSEG * BMF];
__device__ float g_LsegA[NSEG * BMF];

__device__ __forceinline__ uint32_t smem_u32(const void* p) {
  uint32_t a;
  asm("{ .reg .u64 t; cvta.to.shared.u64 t, %1; cvt.u32.u64 %0, t; }"
      : "=r"(a) : "l"(p));
  return a;
}
__device__ __forceinline__ float ex2f(float x) {
  float y; asm("ex2.approx.ftz.f32 %0, %1;" : "=f"(y) : "f"(x)); return y;
}
__device__ __forceinline__ void ldsm4(uint32_t* r, uint32_t addr) {
  asm volatile("ldmatrix.sync.aligned.m8n8.x4.shared.b16 {%0,%1,%2,%3}, [%4];"
               : "=r"(r[0]), "=r"(r[1]), "=r"(r[2]), "=r"(r[3]) : "r"(addr));
}
__device__ __forceinline__ void ldsm4t(uint32_t* r, uint32_t addr) {
  asm volatile("ldmatrix.sync.aligned.m8n8.x4.trans.shared.b16 {%0,%1,%2,%3}, [%4];"
               : "=r"(r[0]), "=r"(r[1]), "=r"(r[2]), "=r"(r[3]) : "r"(addr));
}
__device__ __forceinline__ void mma_bf16(float* d, const uint32_t* a,
                                         const uint32_t* b) {
  asm volatile(
      "mma.sync.aligned.m16n8k16.row.col.f32.bf16.bf16.f32 "
      "{%0,%1,%2,%3}, {%4,%5,%6,%7}, {%8,%9}, {%0,%1,%2,%3};"
      : "+f"(d[0]), "+f"(d[1]), "+f"(d[2]), "+f"(d[3])
      : "r"(a[0]), "r"(a[1]), "r"(a[2]), "r"(a[3]), "r"(b[0]), "r"(b[1]));
}
__device__ __forceinline__ void mma_f16(float* d, const uint32_t* a,
                                        const uint32_t* b) {
  asm volatile(
      "mma.sync.aligned.m16n8k16.row.col.f32.f16.f16.f32 "
      "{%0,%1,%2,%3}, {%4,%5,%6,%7}, {%8,%9}, {%0,%1,%2,%3};"
      : "+f"(d[0]), "+f"(d[1]), "+f"(d[2]), "+f"(d[3])
      : "r"(a[0]), "r"(a[1]), "r"(a[2]), "r"(a[3]), "r"(b[0]), "r"(b[1]));
}
__device__ __forceinline__ void cpa16(uint32_t dst, const void* src) {
  asm volatile("cp.async.cg.shared.global [%0], [%1], 16;" :: "r"(dst), "l"(src));
}
#define CP_COMMIT() asm volatile("cp.async.commit_group;" ::: "memory")
#define CP_WAIT1() asm volatile("cp.async.wait_group 1;" ::: "memory")
#define CP_WAIT0() asm volatile("cp.async.wait_group 0;" ::: "memory")

// ---------------------------------------------------------------------------
// Prep kernel: split x and W (fp32 -> bf16 hi/lo) in one launch.
// ---------------------------------------------------------------------------
__global__ __launch_bounds__(256) void split_all_kernel(
    const float* __restrict__ x, const float* __restrict__ Wq,
    const float* __restrict__ Wk, const float* __restrict__ Wv) {
  int b = blockIdx.x;
  const float* src;
  __nv_bfloat16 *dhi, *dlo;
  size_t i;
  float sc = 1.0f;
  if (b < NTOK * DIN / 1024) {
    src = x;  dhi = g_Xhi;  dlo = g_Xlo;
    i = ((size_t)b * 256 + threadIdx.x) * 4;
  } else {
    int w = b - NTOK * DIN / 1024;
    int y = w >> 7, bx = w & 127;
    if (y == 0) { src = Wq; sc = 0.08838834764831845f * 1.4426950408889634f; }
    else if (y == 1) src = Wk;
    else src = Wv;
    i = ((size_t)bx * 256 + threadIdx.x) * 4;
    dhi = g_Whi + (size_t)y * DIN * DH;
    dlo = g_Wlo + (size_t)y * DIN * DH;
  }
  float4 v = *(const float4*)(src + i);
  v.x *= sc; v.y *= sc; v.z *= sc; v.w *= sc;
  __nv_bfloat16 h0 = __float2bfloat16_rn(v.x), h1 = __float2bfloat16_rn(v.y);
  __nv_bfloat16 h2 = __float2bfloat16_rn(v.z), h3 = __float2bfloat16_rn(v.w);
  __nv_bfloat162 hh0 = __halves2bfloat162(h0, h1), hh1 = __halves2bfloat162(h2, h3);
  __nv_bfloat162 ll0 = __halves2bfloat162(
      __float2bfloat16_rn(v.x - __bfloat162float(h0)),
      __float2bfloat16_rn(v.y - __bfloat162float(h1)));
  __nv_bfloat162 ll1 = __halves2bfloat162(
      __float2bfloat16_rn(v.z - __bfloat162float(h2)),
      __float2bfloat16_rn(v.w - __bfloat162float(h3)));
  *(uint2*)&dhi[i] = make_uint2(*(uint32_t*)&hh0, *(uint32_t*)&hh1);
  *(uint2*)&dlo[i] = make_uint2(*(uint32_t*)&ll0, *(uint32_t*)&ll1);
}

// ---------------------------------------------------------------------------
// Kernel 1: QKV projection GEMM, BM=64, 128 threads, 2 CTAs/SM.
// ---------------------------------------------------------------------------
#define XROW 144
#define WROW 272
#define PSTAGE 53248
#define SMEM_PROJ (2 * PSTAGE)

__device__ __forceinline__ void proj_issue(int tid, int mb, int y, int k0,
                                           uint32_t dstbase) {
#pragma unroll
  for (int it = 0; it < 8; it++) {
    int idx = tid + it * 128;
    int arr = idx >> 9, w = idx & 511;
    int r = w >> 3, c = w & 7;
    const __nv_bfloat16* src = (arr ? g_Xlo : g_Xhi) +
                               (size_t)(mb + r) * DIN + k0 + c * 8;
    cpa16(dstbase + arr * 9216 + r * XROW + c * 16, src);
  }
#pragma unroll
  for (int it = 0; it < 16; it++) {
    int idx = tid + it * 128;
    int arr = idx >> 10, w = idx & 1023;
    int r = w >> 4, c = w & 15;
    const __nv_bfloat16* src = (arr ? g_Wlo : g_Whi) +
                               (size_t)y * DIN * DH + (size_t)(k0 + r) * DH + c * 8;
    cpa16(dstbase + 18432 + arr * 17408 + r * WROW + c * 16, src);
  }
}

__global__ __launch_bounds__(128, 2) void qkv_proj_mma() {
  extern __shared__ char smc[];
  const int tid = threadIdx.x;
  const int lane = tid & 31, warp = tid >> 5;
  const int wm = warp * 16;
  const int mb = blockIdx.x * 64;
  const int y = blockIdx.y;
  const uint32_t sb = smem_u32(smc);

  float acc[16][4];
#pragma unroll
  for (int f = 0; f < 16; f++)
#pragma unroll
    for (int e = 0; e < 4; e++) acc[f][e] = 0.f;

  const uint32_t ah_addr = sb + (uint32_t)(wm + (lane & 15)) * XROW +
                           (lane >> 4) * 16;
  const uint32_t bh_addr = sb + 18432 +
                           (uint32_t)((lane & 7) + ((lane >> 3) & 1) * 8) * WROW +
                           ((lane >> 4) & 1) * 16;

  proj_issue(tid, mb, y, 0, sb);           CP_COMMIT();
  proj_issue(tid, mb, y, 64, sb + PSTAGE); CP_COMMIT();

  const int NT = DIN / 64;   // 16
  for (int t = 0; t < NT; t++) {
    if (t + 1 < NT) CP_WAIT1(); else CP_WAIT0();
    __syncthreads();
    uint32_t bo = (uint32_t)(t & 1) * PSTAGE;
#pragma unroll
    for (int j = 0; j < 4; j++) {
      uint32_t ah[4], al[4];
      ldsm4(ah, ah_addr + bo + j * 32);
      ldsm4(al, ah_addr + bo + 9216 + j * 32);
#pragma unroll
      for (int f2 = 0; f2 < 8; f2++) {
        uint32_t bh[4], bl[4];
        uint32_t a = bh_addr + bo + (uint32_t)(j * 16) * WROW + f2 * 32;
        ldsm4t(bh, a);
        ldsm4t(bl, a + 17408);
        mma_bf16(acc[2 * f2], ah, bh);
        mma_bf16(acc[2 * f2 + 1], ah, bh + 2);
        mma_bf16(acc[2 * f2], ah, bl);
        mma_bf16(acc[2 * f2 + 1], ah, bl + 2);
        mma_bf16(acc[2 * f2], al, bh);
        mma_bf16(acc[2 * f2 + 1], al, bh + 2);
      }
    }
    __syncthreads();
    if (t + 2 < NT) { proj_issue(tid, mb, y, (t + 2) * 64, sb + bo); }
    CP_COMMIT();
  }

  int r0 = mb + wm + (lane >> 2), r1 = r0 + 8;
  int cb = 2 * (lane & 3);
#pragma unroll
  for (int f = 0; f < 16; f++) {
    int c = 8 * f + cb;
    float v0 = acc[f][0], v1 = acc[f][1], v2 = acc[f][2], v3 = acc[f][3];
    if (y == 2) {
      *(__half2*)&g_Vhi[(size_t)r0 * DH + c] = __floats2half2_rn(v0, v1);
      *(__half2*)&g_Vhi[(size_t)r1 * DH + c] = __floats2half2_rn(v2, v3);
    } else {
      __nv_bfloat16 h0 = __float2bfloat16_rn(v0), h1 = __float2bfloat16_rn(v1);
      __nv_bfloat16 h2 = __float2bfloat16_rn(v2), h3 = __float2bfloat16_rn(v3);
      __nv_bfloat16* hi = y ? g_Khi : g_Qhi;
      __nv_bfloat16* lo = y ? g_Klo : g_Qlo;
      *(__nv_bfloat162*)&hi[(size_t)r0 * DH + c] = __halves2bfloat162(h0, h1);
      *(__nv_bfloat162*)&hi[(size_t)r1 * DH + c] = __halves2bfloat162(h2, h3);
      *(__nv_bfloat162*)&lo[(size_t)r0 * DH + c] = __halves2bfloat162(
          __float2bfloat16_rn(v0 - __bfloat162float(h0)),
          __float2bfloat16_rn(v1 - __bfloat162float(h1)));
      *(__nv_bfloat162*)&lo[(size_t)r1 * DH + c] = __halves2bfloat162(
          __float2bfloat16_rn(v2 - __bfloat162float(h2)),
          __float2bfloat16_rn(v3 - __bfloat162float(h3)));
    }
  }
}

// ---------------------------------------------------------------------------
// Kernel 2: flash attention, BM=192 (12 warps, 384 threads), BN=64,
// flat-scheduled over 148 CTAs (5504 tiles, 37-38 per CTA, <=2 segments).
// 2-stage cp.async ring + resident Q in smem (fragments re-LDSM'd per tile
// to fit the 170-reg budget at 384 threads).  PV = Phi * Vhi (fp16).
// smem: ring 2 x 52224 + Qhi 52224 + Qlo 52224 = 208896 B.
// ---------------------------------------------------------------------------
#define ROWB 272
#define SKLO 17408
#define SVHI 34816
#define FSTAGE 52224
#define QOFF (2 * FSTAGE)
#define SMEM_FLASH (4 * FSTAGE)
#define FTHR 384

__device__ __forceinline__ void flash_issue(int tid, int n0, uint32_t dstbase) {
#pragma unroll
  for (int it = 0; it < 8; it++) {
    int idx = tid + it * FTHR;
    int arr = idx >> 10, w = idx & 1023;
    int r = w >> 4, c = w & 15;
    const __nv_bfloat16* srcb;
    if (arr == 0)      srcb = g_Khi;
    else if (arr == 1) srcb = g_Klo;
    else               srcb = (const __nv_bfloat16*)g_Vhi;
    cpa16(dstbase + arr * 17408 + r * ROWB + c * 16,
          srcb + (size_t)(n0 + r) * DH + c * 8);
  }
}

// S = Q K^T for one key tile (Q fragments re-loaded from resident smem).
__device__ __forceinline__ void s_mma_tile(float sf[8][4], uint32_t kbase,
                                           uint32_t qh_addr, uint32_t ql_addr) {
#pragma unroll
  for (int f = 0; f < 8; f++)
#pragma unroll
    for (int e = 0; e < 4; e++) sf[f][e] = 0.f;
#pragma unroll
  for (int j = 0; j < 8; j++) {
    uint32_t qh[4], ql[4];
    ldsm4(qh, qh_addr + j * 32);
    ldsm4(ql, ql_addr + j * 32);
#pragma unroll
    for (int f2 = 0; f2 < 4; f2++) {
      uint32_t bh[4], bl[4];
      uint32_t a = kbase + (uint32_t)(f2 * 16) * ROWB + j * 32;
      ldsm4(bh, a);
      ldsm4(bl, a + SKLO);
      mma_bf16(sf[2 * f2], qh, bh);
      mma_bf16(sf[2 * f2 + 1], qh, bh + 2);
      mma_bf16(sf[2 * f2], qh, bl);
      mma_bf16(sf[2 * f2 + 1], qh, bl + 2);
      mma_bf16(sf[2 * f2], ql, bh);
      mma_bf16(sf[2 * f2 + 1], ql, bh + 2);
    }
  }
}

// Online softmax (base-2 logits) + conditional O rescale + PV accumulate.
__device__ __forceinline__ void softmax_pv(float sf[8][4], float of[16][4],
                                           float& mrow0, float& mrow1,
                                           float& l0, float& l1,
                                           uint32_t vbase) {
  float mx0 = sf[0][0], mx1 = sf[0][2];
#pragma unroll
  for (int f = 0; f < 8; f++) {
    mx0 = fmaxf(mx0, fmaxf(sf[f][0], sf[f][1]));
    mx1 = fmaxf(mx1, fmaxf(sf[f][2], sf[f][3]));
  }
  mx0 = fmaxf(mx0, __shfl_xor_sync(0xffffffffu, mx0, 1));
  mx0 = fmaxf(mx0, __shfl_xor_sync(0xffffffffu, mx0, 2));
  mx1 = fmaxf(mx1, __shfl_xor_sync(0xffffffffu, mx1, 1));
  mx1 = fmaxf(mx1, __shfl_xor_sync(0xffffffffu, mx1, 2));

  float mn0 = fmaxf(mrow0, mx0), mn1 = fmaxf(mrow1, mx1);
  float a0 = ex2f(mrow0 - mn0), a1 = ex2f(mrow1 - mn1);
  mrow0 = mn0; mrow1 = mn1;

  float s0 = 0.f, s1 = 0.f;
#pragma unroll
  for (int f = 0; f < 8; f++) {
    sf[f][0] = ex2f(sf[f][0] - mn0);
    sf[f][1] = ex2f(sf[f][1] - mn0);
    sf[f][2] = ex2f(sf[f][2] - mn1);
    sf[f][3] = ex2f(sf[f][3] - mn1);
    s0 += sf[f][0] + sf[f][1];
    s1 += sf[f][2] + sf[f][3];
  }
  s0 += __shfl_xor_sync(0xffffffffu, s0, 1);
  s0 += __shfl_xor_sync(0xffffffffu, s0, 2);
  s1 += __shfl_xor_sync(0xffffffffu, s1, 1);
  s1 += __shfl_xor_sync(0xffffffffu, s1, 2);
  l0 = l0 * a0 + s0;
  l1 = l1 * a1 + s1;

  if (!__all_sync(0xffffffffu, (__float_as_uint(a0) == 0x3f800000u) &&
                              (__float_as_uint(a1) == 0x3f800000u))) {
#pragma unroll
    for (int f = 0; f < 16; f++) {
      of[f][0] *= a0;  of[f][1] *= a0;
      of[f][2] *= a1;  of[f][3] *= a1;
    }
  }

#pragma unroll
  for (int j2 = 0; j2 < 4; j2++) {
    uint32_t ph[4];
    __half2 h;
    h = __floats2half2_rn(sf[2 * j2][0], sf[2 * j2][1]);         ph[0] = *(uint32_t*)&h;
    h = __floats2half2_rn(sf[2 * j2][2], sf[2 * j2][3]);         ph[1] = *(uint32_t*)&h;
    h = __floats2half2_rn(sf[2 * j2 + 1][0], sf[2 * j2 + 1][1]); ph[2] = *(uint32_t*)&h;
    h = __floats2half2_rn(sf[2 * j2 + 1][2], sf[2 * j2 + 1][3]); ph[3] = *(uint32_t*)&h;
    uint32_t ka = vbase + (uint32_t)(j2 * 16) * ROWB;
#pragma unroll
    for (int f2 = 0; f2 < 8; f2++) {
      uint32_t bv[4];
      ldsm4t(bv, ka + f2 * 32);
      mma_f16(of[2 * f2], ph, bv);
      mma_f16(of[2 * f2 + 1], ph, bv + 2);
    }
  }
}

__global__ __launch_bounds__(FTHR, 1) void flash_mma(int dummy) {
  extern __shared__ char smc[];
  const int tid = threadIdx.x;
  const int lane = tid & 31, warp = tid >> 5;
  const int wm = warp * 16;
  const int cta = blockIdx.x;
  const uint32_t sb = smem_u32(smc);

  const int Tstart = (cta * FTILES) / NCTA_F;
  const int Tend = ((cta + 1) * FTILES) / NCTA_F;

  // Prime the 2-stage ring (every CTA has >= 37 tiles).
  flash_issue(tid, (Tstart & 127) * 64, sb);                CP_COMMIT();
  flash_issue(tid, ((Tstart + 1) & 127) * 64, sb + FSTAGE); CP_COMMIT();

  const uint32_t qh_addr = sb + QOFF + (uint32_t)(wm + (lane & 15)) * ROWB +
                           (lane >> 4) * 16;
  const uint32_t ql_addr = qh_addr + FSTAGE;
  const uint32_t kaddr = sb + (uint32_t)((lane & 7) + ((lane >> 4) << 3)) * ROWB +
                         ((lane >> 3) & 1) * 16;
  const uint32_t vaddr = sb + (uint32_t)((lane & 7) + (((lane >> 3) & 1) << 3)) * ROWB +
                         ((lane >> 4) & 1) * 16 + SVHI;

  float of[16][4];
  float mrow0 = -1e30f, mrow1 = -1e30f, l0 = 0.f, l1 = 0.f;
  int curblk = -1, seg = 0;

  const int r0 = lane >> 2, r1 = r0 + 8;
  const int cbase = 2 * (lane & 3);

  for (int t = Tstart; t < Tend; t++) {
    if (t < Tend - 1) CP_WAIT1(); else CP_WAIT0();
    __syncthreads();   // stage (t-Tstart)&1 visible to all warps

    // ---- Q-block boundary: flush previous segment, stage new Q ----
    int qb = t >> 7;
    if (qb != curblk) {
      if (curblk >= 0) {
        int slot = cta * 2 + seg;
        float* Ob = g_OpartSeg + (size_t)slot * BMF * DH;
        int lr0 = wm + r0, lr1 = wm + r1;
#pragma unroll
        for (int f = 0; f < 16; f++) {
          *(float2*)&Ob[lr0 * DH + 8 * f + cbase] = make_float2(of[f][0], of[f][1]);
          *(float2*)&Ob[lr1 * DH + 8 * f + cbase] = make_float2(of[f][2], of[f][3]);
        }
        if ((lane & 3) == 0) {
          g_MsegA[slot * BMF + lr0] = mrow0;  g_LsegA[slot * BMF + lr0] = l0;
          g_MsegA[slot * BMF + lr1] = mrow1;  g_LsegA[slot * BMF + lr1] = l1;
        }
        seg = 1;
      }
      curblk = qb;
      // Stage Q rows (row-clamped for the partial final block).
#pragma unroll
      for (int it = 0; it < 16; it++) {
        int idx = tid + it * FTHR;
        int arr = idx >= BMF * 16;              // 3072 items per array
        int w = arr ? idx - BMF * 16 : idx;
        int r = w >> 4, c = w & 15;
        int rr = curblk * BMF + r;
        if (rr > NTOK - 1) rr = NTOK - 1;
        const __nv_bfloat16* src = arr ? g_Qlo : g_Qhi;
        *(float4*)(smc + QOFF + arr * FSTAGE + r * ROWB + c * 16) =
            *(const float4*)(src + (size_t)rr * DH + c * 8);
      }
      __syncthreads();
#pragma unroll
      for (int f = 0; f < 16; f++)
#pragma unroll
        for (int e = 0; e < 4; e++) of[f][e] = 0.f;
      mrow0 = -1e30f; mrow1 = -1e30f; l0 = 0.f; l1 = 0.f;
    }

    const uint32_t bo = (uint32_t)((t - Tstart) & 1) * FSTAGE;

    float sf[8][4];
    s_mma_tile(sf, kaddr + bo, qh_addr, ql_addr);
    softmax_pv(sf, of, mrow0, mrow1, l0, l1, vaddr + bo);

    __syncthreads();   // all warps done with stage bo -> safe to refill
    if (t + 2 < Tend) {
      flash_issue(tid, ((t + 2) & 127) * 64, sb + bo);
    }
    CP_COMMIT();
  }

  // ---- flush final segment ----
  {
    int slot = cta * 2 + seg;
    float* Ob = g_OpartSeg + (size_t)slot * BMF * DH;
    int lr0 = wm + r0, lr1 = wm + r1;
#pragma unroll
    for (int f = 0; f < 16; f++) {
      *(float2*)&Ob[lr0 * DH + 8 * f + cbase] = make_float2(of[f][0], of[f][1]);
      *(float2*)&Ob[lr1 * DH + 8 * f + cbase] = make_float2(of[f][2], of[f][3]);
    }
    if ((lane & 3) == 0) {
      g_MsegA[slot * BMF + lr0] = mrow0;  g_LsegA[slot * BMF + lr0] = l0;
      g_MsegA[slot * BMF + lr1] = mrow1;  g_LsegA[slot * BMF + lr1] = l1;
    }
  }
}

// ---------------------------------------------------------------------------
// Kernel 3: merge — analytic slot enumeration for BM=192 blocks.
// ---------------------------------------------------------------------------
__global__ __launch_bounds__(256) void merge_kernel(float* __restrict__ out) {
  const int tid = threadIdx.x;
  const int row = blockIdx.x * 8 + (tid >> 5);
  const int q = row / BMF;
  const int lrow = row - q * BMF;
  const int c4 = (tid & 31) * 4;

  const int t0 = q * 128, t1 = t0 + 128;

  float m = -1e30f, l = 0.f;
  float4 O = make_float4(0.f, 0.f, 0.f, 0.f);

  int i = (t0 * NCTA_F) / FTILES;
#pragma unroll 1
  for (; i < NCTA_F; i++) {
    int ts = (i * FTILES) / NCTA_F;
    if (ts >= t1) break;
    int te = ((i + 1) * FTILES) / NCTA_F;
    if (te <= t0) continue;
    int slot = 2 * i + (((ts >> 7) == q) ? 0 : 1);

    float ms = g_MsegA[slot * BMF + lrow];
    float ls = g_LsegA[slot * BMF + lrow];
    float4 Os = *(const float4*)&g_OpartSeg[(size_t)slot * BMF * DH +
                                            lrow * DH + c4];
    float mn = fmaxf(m, ms);
    float wa = ex2f(m - mn), wb = ex2f(ms - mn);
    O.x = O.x * wa + Os.x * wb;
    O.y = O.y * wa + Os.y * wb;
    O.z = O.z * wa + Os.z * wb;
    O.w = O.w * wa + Os.w * wb;
    l = l * wa + ls * wb;
    m = mn;
  }

  float inv = 1.0f / l;
  float4 r = make_float4(O.x * inv, O.y * inv, O.z * inv, O.w * inv);
  *(float4*)&out[(size_t)row * DH + c4] = r;
}

// ---------------------------------------------------------------------------
extern "C" void kernel_launch(void* const* d_in, const int* in_sizes, int n_in,
                              void* d_out, int out_size) {
  const float* x  = (const float*)d_in[0];
  const float* Wq = (const float*)d_in[1];
  const float* Wk = (const float*)d_in[2];
  const float* Wv = (const float*)d_in[3];
  float* out = (float*)d_out;

  split_all_kernel<<<NTOK * DIN / 1024 + 3 * (DIN * DH / 1024), 256>>>(
      x, Wq, Wk, Wv);

  cudaFuncSetAttribute(qkv_proj_mma, cudaFuncAttributeMaxDynamicSharedMemorySize,
                       SMEM_PROJ);
  qkv_proj_mma<<<dim3(NTOK / 64, 3, 1), 128, SMEM_PROJ>>>();

  cudaFuncSetAttribute(flash_mma, cudaFuncAttributeMaxDynamicSharedMemorySize,
                       SMEM_FLASH);
  flash_mma<<<NCTA_F, FTHR, SMEM_FLASH>>>(0);

  merge_kernel<<<NTOK / 8, 256>>>(out);
}

// round 14
// speedup vs baseline: 1.2069x; 1.0972x over previous
#include <cuda_runtime.h>
#include <cuda_bf16.h>
#include <cuda_fp16.h>
#include <cstdint>

#define NTOK 8192
#define DIN  1024
#define DH   128

// Pre-split inputs (prep kernel).
__device__ __nv_bfloat16 g_Xhi[NTOK * DIN], g_Xlo[NTOK * DIN];
__device__ __nv_bfloat16 g_Whi[3 * DIN * DH], g_Wlo[3 * DIN * DH];
// Split operands produced by the projection kernel.
__device__ __nv_bfloat16 g_Qhi[NTOK * DH], g_Qlo[NTOK * DH]; // pre-scaled by (1/sqrt d)*log2 e
__device__ __nv_bfloat16 g_Khi[NTOK * DH], g_Klo[NTOK * DH];
__device__ __half        g_Vhi[NTOK * DH];

// Flat-scheduled flash partials: 148 CTAs x <=2 segments (slot = 2*cta + seg).
#define NCTA_F 148
#define NSEG (2 * NCTA_F)            // 296
#define BMF 192                       // rows per Q-block (12 warps x 16)
#define NQB 43                        // ceil(8192 / 192)
#define FTILES (NQB * 128)            // 5504 flat (Q-block, key-tile) units
__device__ float g_OpartSeg[NSEG * BMF * DH];
__device__ float g_MsegA[NSEG * BMF];
__device__ float g_LsegA[NSEG * BMF];

__device__ __forceinline__ uint32_t smem_u32(const void* p) {
  uint32_t a;
  asm("{ .reg .u64 t; cvta.to.shared.u64 t, %1; cvt.u32.u64 %0, t; }"
      : "=r"(a) : "l"(p));
  return a;
}
__device__ __forceinline__ float ex2f(float x) {
  float y; asm("ex2.approx.ftz.f32 %0, %1;" : "=f"(y) : "f"(x)); return y;
}
__device__ __forceinline__ void ldsm4(uint32_t* r, uint32_t addr) {
  asm volatile("ldmatrix.sync.aligned.m8n8.x4.shared.b16 {%0,%1,%2,%3}, [%4];"
               : "=r"(r[0]), "=r"(r[1]), "=r"(r[2]), "=r"(r[3]) : "r"(addr));
}
__device__ __forceinline__ void ldsm4t(uint32_t* r, uint32_t addr) {
  asm volatile("ldmatrix.sync.aligned.m8n8.x4.trans.shared.b16 {%0,%1,%2,%3}, [%4];"
               : "=r"(r[0]), "=r"(r[1]), "=r"(r[2]), "=r"(r[3]) : "r"(addr));
}
__device__ __forceinline__ void mma_bf16(float* d, const uint32_t* a,
                                         const uint32_t* b) {
  asm volatile(
      "mma.sync.aligned.m16n8k16.row.col.f32.bf16.bf16.f32 "
      "{%0,%1,%2,%3}, {%4,%5,%6,%7}, {%8,%9}, {%0,%1,%2,%3};"
      : "+f"(d[0]), "+f"(d[1]), "+f"(d[2]), "+f"(d[3])
      : "r"(a[0]), "r"(a[1]), "r"(a[2]), "r"(a[3]), "r"(b[0]), "r"(b[1]));
}
__device__ __forceinline__ void mma_f16(float* d, const uint32_t* a,
                                        const uint32_t* b) {
  asm volatile(
      "mma.sync.aligned.m16n8k16.row.col.f32.f16.f16.f32 "
      "{%0,%1,%2,%3}, {%4,%5,%6,%7}, {%8,%9}, {%0,%1,%2,%3};"
      : "+f"(d[0]), "+f"(d[1]), "+f"(d[2]), "+f"(d[3])
      : "r"(a[0]), "r"(a[1]), "r"(a[2]), "r"(a[3]), "r"(b[0]), "r"(b[1]));
}
__device__ __forceinline__ void cpa16(uint32_t dst, const void* src) {
  asm volatile("cp.async.cg.shared.global [%0], [%1], 16;" :: "r"(dst), "l"(src));
}
#define CP_COMMIT() asm volatile("cp.async.commit_group;" ::: "memory")
#define CP_WAIT1() asm volatile("cp.async.wait_group 1;" ::: "memory")
#define CP_WAIT0() asm volatile("cp.async.wait_group 0;" ::: "memory")

// ---------------------------------------------------------------------------
// Prep kernel: split x and W (fp32 -> bf16 hi/lo) in one launch.
// ---------------------------------------------------------------------------
__global__ __launch_bounds__(256) void split_all_kernel(
    const float* __restrict__ x, const float* __restrict__ Wq,
    const float* __restrict__ Wk, const float* __restrict__ Wv) {
  int b = blockIdx.x;
  const float* src;
  __nv_bfloat16 *dhi, *dlo;
  size_t i;
  float sc = 1.0f;
  if (b < NTOK * DIN / 1024) {
    src = x;  dhi = g_Xhi;  dlo = g_Xlo;
    i = ((size_t)b * 256 + threadIdx.x) * 4;
  } else {
    int w = b - NTOK * DIN / 1024;
    int y = w >> 7, bx = w & 127;
    if (y == 0) { src = Wq; sc = 0.08838834764831845f * 1.4426950408889634f; }
    else if (y == 1) src = Wk;
    else src = Wv;
    i = ((size_t)bx * 256 + threadIdx.x) * 4;
    dhi = g_Whi + (size_t)y * DIN * DH;
    dlo = g_Wlo + (size_t)y * DIN * DH;
  }
  float4 v = *(const float4*)(src + i);
  v.x *= sc; v.y *= sc; v.z *= sc; v.w *= sc;
  __nv_bfloat16 h0 = __float2bfloat16_rn(v.x), h1 = __float2bfloat16_rn(v.y);
  __nv_bfloat16 h2 = __float2bfloat16_rn(v.z), h3 = __float2bfloat16_rn(v.w);
  __nv_bfloat162 hh0 = __halves2bfloat162(h0, h1), hh1 = __halves2bfloat162(h2, h3);
  __nv_bfloat162 ll0 = __halves2bfloat162(
      __float2bfloat16_rn(v.x - __bfloat162float(h0)),
      __float2bfloat16_rn(v.y - __bfloat162float(h1)));
  __nv_bfloat162 ll1 = __halves2bfloat162(
      __float2bfloat16_rn(v.z - __bfloat162float(h2)),
      __float2bfloat16_rn(v.w - __bfloat162float(h3)));
  *(uint2*)&dhi[i] = make_uint2(*(uint32_t*)&hh0, *(uint32_t*)&hh1);
  *(uint2*)&dlo[i] = make_uint2(*(uint32_t*)&ll0, *(uint32_t*)&ll1);
}

// ---------------------------------------------------------------------------
// Kernel 1: QKV projection GEMM, BM=192 (12 warps, 384 thr), BK=64.
// grid = (43, 3) = 129 CTAs, one wave, 3 warps/SMSP.
// Stage: XHI 0 (192x144=27648), XLO 27648, WHI 55296 (64x272=17408),
// WLO 72704; stage 90112 bytes, two stages = 180224.
// ---------------------------------------------------------------------------
#define XROW 144
#define WROW 272
#define PXLO 27648
#define PWHI 55296
#define PWLO 72704
#define PSTAGE 90112
#define SMEM_PROJ (2 * PSTAGE)
#define PTHR 384

__device__ __forceinline__ void proj_issue(int tid, int mb, int y, int k0,
                                           uint32_t dstbase) {
  // X: 2 arrays x 192 rows x 8 float4 = 3072 items (row-clamped).
#pragma unroll
  for (int it = 0; it < 8; it++) {
    int idx = tid + it * PTHR;
    int arr = idx >> 11, w = idx & 2047;      // 2048 per array? (192*8=1536)
    // 1536 items per array -> use explicit split instead:
    (void)arr; (void)w;
  }
  // Explicit: items 0..1535 -> Xhi, 1536..3071 -> Xlo.
#pragma unroll
  for (int it = 0; it < 8; it++) {
    int idx = tid + it * PTHR;                // 0..3071
    int arr = (idx >= 1536);
    int w = arr ? idx - 1536 : idx;
    int r = w >> 3, c = w & 7;
    int rr = mb + r; if (rr > NTOK - 1) rr = NTOK - 1;
    const __nv_bfloat16* src = (arr ? g_Xlo : g_Xhi) +
                               (size_t)rr * DIN + k0 + c * 8;
    cpa16(dstbase + arr * PXLO + r * XROW + c * 16, src);
  }
  // W: 2 arrays x 64 rows x 16 float4 = 2048 items.
#pragma unroll
  for (int it = 0; it < 6; it++) {
    int idx = tid + it * PTHR;                // 0..2303, guard at 2048
    if (idx < 2048) {
      int arr = idx >> 10, w = idx & 1023;
      int r = w >> 4, c = w & 15;
      const __nv_bfloat16* src = (arr ? g_Wlo : g_Whi) +
                                 (size_t)y * DIN * DH + (size_t)(k0 + r) * DH + c * 8;
      cpa16(dstbase + PWHI + arr * 17408 + r * WROW + c * 16, src);
    }
  }
}

__global__ __launch_bounds__(PTHR, 1) void qkv_proj_mma() {
  extern __shared__ char smc[];
  const int tid = threadIdx.x;
  const int lane = tid & 31, warp = tid >> 5;
  const int wm = warp * 16;
  const int mb = blockIdx.x * 192;
  const int y = blockIdx.y;
  const uint32_t sb = smem_u32(smc);

  float acc[16][4];
#pragma unroll
  for (int f = 0; f < 16; f++)
#pragma unroll
    for (int e = 0; e < 4; e++) acc[f][e] = 0.f;

  const uint32_t ah_addr = sb + (uint32_t)(wm + (lane & 15)) * XROW +
                           (lane >> 4) * 16;
  const uint32_t bh_addr = sb + PWHI +
                           (uint32_t)((lane & 7) + ((lane >> 3) & 1) * 8) * WROW +
                           ((lane >> 4) & 1) * 16;

  proj_issue(tid, mb, y, 0, sb);           CP_COMMIT();
  proj_issue(tid, mb, y, 64, sb + PSTAGE); CP_COMMIT();

  const int NT = DIN / 64;   // 16
  for (int t = 0; t < NT; t++) {
    if (t + 1 < NT) CP_WAIT1(); else CP_WAIT0();
    __syncthreads();
    uint32_t bo = (uint32_t)(t & 1) * PSTAGE;
#pragma unroll
    for (int j = 0; j < 4; j++) {
      uint32_t ah[4], al[4];
      ldsm4(ah, ah_addr + bo + j * 32);
      ldsm4(al, ah_addr + bo + PXLO + j * 32);
#pragma unroll
      for (int f2 = 0; f2 < 8; f2++) {
        uint32_t bh[4], bl[4];
        uint32_t a = bh_addr + bo + (uint32_t)(j * 16) * WROW + f2 * 32;
        ldsm4t(bh, a);
        ldsm4t(bl, a + 17408);
        mma_bf16(acc[2 * f2], ah, bh);
        mma_bf16(acc[2 * f2 + 1], ah, bh + 2);
        mma_bf16(acc[2 * f2], ah, bl);
        mma_bf16(acc[2 * f2 + 1], ah, bl + 2);
        mma_bf16(acc[2 * f2], al, bh);
        mma_bf16(acc[2 * f2 + 1], al, bh + 2);
      }
    }
    __syncthreads();
    if (t + 2 < NT) { proj_issue(tid, mb, y, (t + 2) * 64, sb + bo); }
    CP_COMMIT();
  }

  int r0 = mb + wm + (lane >> 2), r1 = r0 + 8;
  int cb = 2 * (lane & 3);
#pragma unroll
  for (int f = 0; f < 16; f++) {
    int c = 8 * f + cb;
    float v0 = acc[f][0], v1 = acc[f][1], v2 = acc[f][2], v3 = acc[f][3];
    if (y == 2) {
      if (r0 < NTOK)
        *(__half2*)&g_Vhi[(size_t)r0 * DH + c] = __floats2half2_rn(v0, v1);
      if (r1 < NTOK)
        *(__half2*)&g_Vhi[(size_t)r1 * DH + c] = __floats2half2_rn(v2, v3);
    } else {
      __nv_bfloat16* hi = y ? g_Khi : g_Qhi;
      __nv_bfloat16* lo = y ? g_Klo : g_Qlo;
      if (r0 < NTOK) {
        __nv_bfloat16 h0 = __float2bfloat16_rn(v0), h1 = __float2bfloat16_rn(v1);
        *(__nv_bfloat162*)&hi[(size_t)r0 * DH + c] = __halves2bfloat162(h0, h1);
        *(__nv_bfloat162*)&lo[(size_t)r0 * DH + c] = __halves2bfloat162(
            __float2bfloat16_rn(v0 - __bfloat162float(h0)),
            __float2bfloat16_rn(v1 - __bfloat162float(h1)));
      }
      if (r1 < NTOK) {
        __nv_bfloat16 h2 = __float2bfloat16_rn(v2), h3 = __float2bfloat16_rn(v3);
        *(__nv_bfloat162*)&hi[(size_t)r1 * DH + c] = __halves2bfloat162(h2, h3);
        *(__nv_bfloat162*)&lo[(size_t)r1 * DH + c] = __halves2bfloat162(
            __float2bfloat16_rn(v2 - __bfloat162float(h2)),
            __float2bfloat16_rn(v3 - __bfloat162float(h3)));
      }
    }
  }
}

// ---------------------------------------------------------------------------
// Kernel 2: flash attention, BM=192 (12 warps, 384 threads), BN=64,
// flat-scheduled over 148 CTAs (5504 tiles, 37-38 per CTA, <=2 segments).
// 2-stage cp.async ring + resident Q in smem.  PV = Phi * Vhi (fp16).
// ---------------------------------------------------------------------------
#define ROWB 272
#define SKLO 17408
#define SVHI 34816
#define FSTAGE 52224
#define QOFF (2 * FSTAGE)
#define SMEM_FLASH (4 * FSTAGE)
#define FTHR 384

__device__ __forceinline__ void flash_issue(int tid, int n0, uint32_t dstbase) {
#pragma unroll
  for (int it = 0; it < 8; it++) {
    int idx = tid + it * FTHR;
    int arr = idx >> 10, w = idx & 1023;
    int r = w >> 4, c = w & 15;
    const __nv_bfloat16* srcb;
    if (arr == 0)      srcb = g_Khi;
    else if (arr == 1) srcb = g_Klo;
    else               srcb = (const __nv_bfloat16*)g_Vhi;
    cpa16(dstbase + arr * 17408 + r * ROWB + c * 16,
          srcb + (size_t)(n0 + r) * DH + c * 8);
  }
}

__device__ __forceinline__ void s_mma_tile(float sf[8][4], uint32_t kbase,
                                           uint32_t qh_addr, uint32_t ql_addr) {
#pragma unroll
  for (int f = 0; f < 8; f++)
#pragma unroll
    for (int e = 0; e < 4; e++) sf[f][e] = 0.f;
#pragma unroll
  for (int j = 0; j < 8; j++) {
    uint32_t qh[4], ql[4];
    ldsm4(qh, qh_addr + j * 32);
    ldsm4(ql, ql_addr + j * 32);
#pragma unroll
    for (int f2 = 0; f2 < 4; f2++) {
      uint32_t bh[4], bl[4];
      uint32_t a = kbase + (uint32_t)(f2 * 16) * ROWB + j * 32;
      ldsm4(bh, a);
      ldsm4(bl, a + SKLO);
      mma_bf16(sf[2 * f2], qh, bh);
      mma_bf16(sf[2 * f2 + 1], qh, bh + 2);
      mma_bf16(sf[2 * f2], qh, bl);
      mma_bf16(sf[2 * f2 + 1], qh, bl + 2);
      mma_bf16(sf[2 * f2], ql, bh);
      mma_bf16(sf[2 * f2 + 1], ql, bh + 2);
    }
  }
}

__device__ __forceinline__ void softmax_pv(float sf[8][4], float of[16][4],
                                           float& mrow0, float& mrow1,
                                           float& l0, float& l1,
                                           uint32_t vbase) {
  float mx0 = sf[0][0], mx1 = sf[0][2];
#pragma unroll
  for (int f = 0; f < 8; f++) {
    mx0 = fmaxf(mx0, fmaxf(sf[f][0], sf[f][1]));
    mx1 = fmaxf(mx1, fmaxf(sf[f][2], sf[f][3]));
  }
  mx0 = fmaxf(mx0, __shfl_xor_sync(0xffffffffu, mx0, 1));
  mx0 = fmaxf(mx0, __shfl_xor_sync(0xffffffffu, mx0, 2));
  mx1 = fmaxf(mx1, __shfl_xor_sync(0xffffffffu, mx1, 1));
  mx1 = fmaxf(mx1, __shfl_xor_sync(0xffffffffu, mx1, 2));

  float mn0 = fmaxf(mrow0, mx0), mn1 = fmaxf(mrow1, mx1);
  float a0 = ex2f(mrow0 - mn0), a1 = ex2f(mrow1 - mn1);
  mrow0 = mn0; mrow1 = mn1;

  float s0 = 0.f, s1 = 0.f;
#pragma unroll
  for (int f = 0; f < 8; f++) {
    sf[f][0] = ex2f(sf[f][0] - mn0);
    sf[f][1] = ex2f(sf[f][1] - mn0);
    sf[f][2] = ex2f(sf[f][2] - mn1);
    sf[f][3] = ex2f(sf[f][3] - mn1);
    s0 += sf[f][0] + sf[f][1];
    s1 += sf[f][2] + sf[f][3];
  }
  s0 += __shfl_xor_sync(0xffffffffu, s0, 1);
  s0 += __shfl_xor_sync(0xffffffffu, s0, 2);
  s1 += __shfl_xor_sync(0xffffffffu, s1, 1);
  s1 += __shfl_xor_sync(0xffffffffu, s1, 2);
  l0 = l0 * a0 + s0;
  l1 = l1 * a1 + s1;

  if (!__all_sync(0xffffffffu, (__float_as_uint(a0) == 0x3f800000u) &&
                              (__float_as_uint(a1) == 0x3f800000u))) {
#pragma unroll
    for (int f = 0; f < 16; f++) {
      of[f][0] *= a0;  of[f][1] *= a0;
      of[f][2] *= a1;  of[f][3] *= a1;
    }
  }

#pragma unroll
  for (int j2 = 0; j2 < 4; j2++) {
    uint32_t ph[4];
    __half2 h;
    h = __floats2half2_rn(sf[2 * j2][0], sf[2 * j2][1]);         ph[0] = *(uint32_t*)&h;
    h = __floats2half2_rn(sf[2 * j2][2], sf[2 * j2][3]);         ph[1] = *(uint32_t*)&h;
    h = __floats2half2_rn(sf[2 * j2 + 1][0], sf[2 * j2 + 1][1]); ph[2] = *(uint32_t*)&h;
    h = __floats2half2_rn(sf[2 * j2 + 1][2], sf[2 * j2 + 1][3]); ph[3] = *(uint32_t*)&h;
    uint32_t ka = vbase + (uint32_t)(j2 * 16) * ROWB;
#pragma unroll
    for (int f2 = 0; f2 < 8; f2++) {
      uint32_t bv[4];
      ldsm4t(bv, ka + f2 * 32);
      mma_f16(of[2 * f2], ph, bv);
      mma_f16(of[2 * f2 + 1], ph, bv + 2);
    }
  }
}

__global__ __launch_bounds__(FTHR, 1) void flash_mma(int dummy) {
  extern __shared__ char smc[];
  const int tid = threadIdx.x;
  const int lane = tid & 31, warp = tid >> 5;
  const int wm = warp * 16;
  const int cta = blockIdx.x;
  const uint32_t sb = smem_u32(smc);

  const int Tstart = (cta * FTILES) / NCTA_F;
  const int Tend = ((cta + 1) * FTILES) / NCTA_F;

  flash_issue(tid, (Tstart & 127) * 64, sb);                CP_COMMIT();
  flash_issue(tid, ((Tstart + 1) & 127) * 64, sb + FSTAGE); CP_COMMIT();

  const uint32_t qh_addr = sb + QOFF + (uint32_t)(wm + (lane & 15)) * ROWB +
                           (lane >> 4) * 16;
  const uint32_t ql_addr = qh_addr + FSTAGE;
  const uint32_t kaddr = sb + (uint32_t)((lane & 7) + ((lane >> 4) << 3)) * ROWB +
                         ((lane >> 3) & 1) * 16;
  const uint32_t vaddr = sb + (uint32_t)((lane & 7) + (((lane >> 3) & 1) << 3)) * ROWB +
                         ((lane >> 4) & 1) * 16 + SVHI;

  float of[16][4];
  float mrow0 = -1e30f, mrow1 = -1e30f, l0 = 0.f, l1 = 0.f;
  int curblk = -1, seg = 0;

  const int r0 = lane >> 2, r1 = r0 + 8;
  const int cbase = 2 * (lane & 3);

  for (int t = Tstart; t < Tend; t++) {
    if (t < Tend - 1) CP_WAIT1(); else CP_WAIT0();
    __syncthreads();

    int qb = t >> 7;
    if (qb != curblk) {
      if (curblk >= 0) {
        int slot = cta * 2 + seg;
        float* Ob = g_OpartSeg + (size_t)slot * BMF * DH;
        int lr0 = wm + r0, lr1 = wm + r1;
#pragma unroll
        for (int f = 0; f < 16; f++) {
          *(float2*)&Ob[lr0 * DH + 8 * f + cbase] = make_float2(of[f][0], of[f][1]);
          *(float2*)&Ob[lr1 * DH + 8 * f + cbase] = make_float2(of[f][2], of[f][3]);
        }
        if ((lane & 3) == 0) {
          g_MsegA[slot * BMF + lr0] = mrow0;  g_LsegA[slot * BMF + lr0] = l0;
          g_MsegA[slot * BMF + lr1] = mrow1;  g_LsegA[slot * BMF + lr1] = l1;
        }
        seg = 1;
      }
      curblk = qb;
#pragma unroll
      for (int it = 0; it < 16; it++) {
        int idx = tid + it * FTHR;
        int arr = idx >= BMF * 16;
        int w = arr ? idx - BMF * 16 : idx;
        int r = w >> 4, c = w & 15;
        int rr = curblk * BMF + r;
        if (rr > NTOK - 1) rr = NTOK - 1;
        const __nv_bfloat16* src = arr ? g_Qlo : g_Qhi;
        *(float4*)(smc + QOFF + arr * FSTAGE + r * ROWB + c * 16) =
            *(const float4*)(src + (size_t)rr * DH + c * 8);
      }
      __syncthreads();
#pragma unroll
      for (int f = 0; f < 16; f++)
#pragma unroll
        for (int e = 0; e < 4; e++) of[f][e] = 0.f;
      mrow0 = -1e30f; mrow1 = -1e30f; l0 = 0.f; l1 = 0.f;
    }

    const uint32_t bo = (uint32_t)((t - Tstart) & 1) * FSTAGE;

    float sf[8][4];
    s_mma_tile(sf, kaddr + bo, qh_addr, ql_addr);
    softmax_pv(sf, of, mrow0, mrow1, l0, l1, vaddr + bo);

    __syncthreads();
    if (t + 2 < Tend) {
      flash_issue(tid, ((t + 2) & 127) * 64, sb + bo);
    }
    CP_COMMIT();
  }

  {
    int slot = cta * 2 + seg;
    float* Ob = g_OpartSeg + (size_t)slot * BMF * DH;
    int lr0 = wm + r0, lr1 = wm + r1;
#pragma unroll
    for (int f = 0; f < 16; f++) {
      *(float2*)&Ob[lr0 * DH + 8 * f + cbase] = make_float2(of[f][0], of[f][1]);
      *(float2*)&Ob[lr1 * DH + 8 * f + cbase] = make_float2(of[f][2], of[f][3]);
    }
    if ((lane & 3) == 0) {
      g_MsegA[slot * BMF + lr0] = mrow0;  g_LsegA[slot * BMF + lr0] = l0;
      g_MsegA[slot * BMF + lr1] = mrow1;  g_LsegA[slot * BMF + lr1] = l1;
    }
  }
}

// ---------------------------------------------------------------------------
// Kernel 3: merge — analytic slot enumeration for BM=192 blocks.
// ---------------------------------------------------------------------------
__global__ __launch_bounds__(256) void merge_kernel(float* __restrict__ out) {
  const int tid = threadIdx.x;
  const int row = blockIdx.x * 8 + (tid >> 5);
  const int q = row / BMF;
  const int lrow = row - q * BMF;
  const int c4 = (tid & 31) * 4;

  const int t0 = q * 128, t1 = t0 + 128;

  float m = -1e30f, l = 0.f;
  float4 O = make_float4(0.f, 0.f, 0.f, 0.f);

  int i = (t0 * NCTA_F) / FTILES;
#pragma unroll 1
  for (; i < NCTA_F; i++) {
    int ts = (i * FTILES) / NCTA_F;
    if (ts >= t1) break;
    int te = ((i + 1) * FTILES) / NCTA_F;
    if (te <= t0) continue;
    int slot = 2 * i + (((ts >> 7) == q) ? 0 : 1);

    float ms = g_MsegA[slot * BMF + lrow];
    float ls = g_LsegA[slot * BMF + lrow];
    float4 Os = *(const float4*)&g_OpartSeg[(size_t)slot * BMF * DH +
                                            lrow * DH + c4];
    float mn = fmaxf(m, ms);
    float wa = ex2f(m - mn), wb = ex2f(ms - mn);
    O.x = O.x * wa + Os.x * wb;
    O.y = O.y * wa + Os.y * wb;
    O.z = O.z * wa + Os.z * wb;
    O.w = O.w * wa + Os.w * wb;
    l = l * wa + ls * wb;
    m = mn;
  }

  float inv = 1.0f / l;
  float4 r = make_float4(O.x * inv, O.y * inv, O.z * inv, O.w * inv);
  *(float4*)&out[(size_t)row * DH + c4] = r;
}

// ---------------------------------------------------------------------------
extern "C" void kernel_launch(void* const* d_in, const int* in_sizes, int n_in,
                              void* d_out, int out_size) {
  const float* x  = (const float*)d_in[0];
  const float* Wq = (const float*)d_in[1];
  const float* Wk = (const float*)d_in[2];
  const float* Wv = (const float*)d_in[3];
  float* out = (float*)d_out;

  split_all_kernel<<<NTOK * DIN / 1024 + 3 * (DIN * DH / 1024), 256>>>(
      x, Wq, Wk, Wv);

  cudaFuncSetAttribute(qkv_proj_mma, cudaFuncAttributeMaxDynamicSharedMemorySize,
                       SMEM_PROJ);
  qkv_proj_mma<<<dim3(NQB, 3, 1), PTHR, SMEM_PROJ>>>();

  cudaFuncSetAttribute(flash_mma, cudaFuncAttributeMaxDynamicSharedMemorySize,
                       SMEM_FLASH);
  flash_mma<<<NCTA_F, FTHR, SMEM_FLASH>>>(0);

  merge_kernel<<<NTOK / 8, 256>>>(out);
}